// round 10
// baseline (speedup 1.0000x reference)
#include <cuda_runtime.h>
#include <cuda_bf16.h>
#include <math.h>
#include <stdint.h>

// Problem dims
#define BB 4
#define SS 1024
#define DD 1024
#define FF 2048
#define HH 16
#define EE 8
#define DK 64
#define TT (BB*SS)          // 4096 tokens
typedef long long ll;

// ---------------- static device scratch ----------------
__device__ float g_x2a[TT*DD];
__device__ float g_qkv[3*TT*DD];                // q,k slices (v slice unused)
__device__ float g_vt[TT*DD];                   // V transposed per (b): [b*DD+hd][s]
__device__ float g_ctx[TT*DD];
__device__ float g_xres[TT*DD];
__device__ float g_x2b[TT*DD];
__device__ float g_emid[(size_t)EE*TT*FF];      // MoE mid
__device__ float g_moe[(size_t)EE*TT*DD];
__device__ unsigned g_mb[(size_t)TT*32];        // bitpacked mask: row*32 words
__device__ int   g_counts[EE];
__device__ int   g_etok[EE*TT];
__device__ int   g_texp[TT*2];
__device__ int   g_tslot[TT*2];
__device__ float g_tw[TT*2];

// ---------------- helpers ----------------
__device__ __forceinline__ float blockReduceSum(float v, float* sh) {
    int tid = threadIdx.x;
    sh[tid] = v; __syncthreads();
    for (int s = 128; s > 0; s >>= 1) {
        if (tid < s) sh[tid] += sh[tid + s];
        __syncthreads();
    }
    float r = sh[0]; __syncthreads();
    return r;
}
__device__ __forceinline__ void mma_tf32(float4& d, const uint32_t* a, const uint32_t* b) {
    asm volatile(
        "mma.sync.aligned.m16n8k8.row.col.f32.tf32.tf32.f32 "
        "{%0,%1,%2,%3}, {%4,%5,%6,%7}, {%8,%9}, {%0,%1,%2,%3};"
        : "+f"(d.x), "+f"(d.y), "+f"(d.z), "+f"(d.w)
        : "r"(a[0]), "r"(a[1]), "r"(a[2]), "r"(a[3]), "r"(b[0]), "r"(b[1]));
}
__device__ __forceinline__ void cpa16(float* dst, const float* src, int sz) {
    uint32_t d = (uint32_t)__cvta_generic_to_shared(dst);
    asm volatile("cp.async.cg.shared.global [%0], [%1], 16, %2;\n"
                 :: "r"(d), "l"(src), "r"(sz));
}
__device__ __forceinline__ void ldsm4(uint32_t* d, const float* p) {
    uint32_t a = (uint32_t)__cvta_generic_to_shared(p);
    asm volatile("ldmatrix.sync.aligned.m8n8.x4.shared.b16 {%0,%1,%2,%3}, [%4];"
                 : "=r"(d[0]), "=r"(d[1]), "=r"(d[2]), "=r"(d[3]) : "r"(a));
}
__device__ __forceinline__ float siluf(float x) {
    return x / (1.f + __expf(-x));
}

// ---------------- LayerNorm ----------------
__global__ void ln_k(const float* __restrict__ x, const float* __restrict__ g,
                     const float* __restrict__ b, float* __restrict__ out) {
    __shared__ float sh[256];
    int r = blockIdx.x;
    const float* row = x + (size_t)r * DD;
    float s = 0.f;
    for (int i = threadIdx.x; i < DD; i += 256) s += row[i];
    float mean = blockReduceSum(s, sh) * (1.0f / DD);
    float v = 0.f;
    for (int i = threadIdx.x; i < DD; i += 256) {
        float d = row[i] - mean; v += d * d;
    }
    float var = blockReduceSum(v, sh) * (1.0f / DD);
    float inv = rsqrtf(var + 1e-5f);
    float* o = out + (size_t)r * DD;
    for (int i = threadIdx.x; i < DD; i += 256)
        o[i] = (row[i] - mean) * inv * g[i] + b[i];
}

// ---------------- mask bitpack ----------------
__global__ void packmask_k(const int* __restrict__ mask, unsigned* __restrict__ mb) {
    int wid = threadIdx.x >> 5, lane = threadIdx.x & 31;
    ll row = (ll)blockIdx.x * 8 + wid;
    const int* mrow = mask + row * SS;
#pragma unroll
    for (int w = 0; w < 32; w++) {
        unsigned word = __ballot_sync(0xffffffff, mrow[w * 32 + lane] != 0);
        if (lane == 0) mb[row * 32 + w] = word;
    }
}

// ================= 3-stage pipelined tensor-core tf32 GEMM (single) =================
template<int BM, int BN, int WGM, int WGN, int EPI, int GATHER, int MPZ>
__global__ void __launch_bounds__(WGM*WGN*32, (WGM*WGN*32 == 256) ? 2 : 1)
tcg(const float* __restrict__ A, int lda, ll sAz,
    const float* __restrict__ B0, int ldb, ll sBz,
    const float* __restrict__ bias0, ll sBiasZ,
    const float* __restrict__ S,
    float* __restrict__ C, int ldc, ll sCz,
    int M, const int* __restrict__ Mptr, int Kd,
    const int* __restrict__ tok) {
    constexpr int NTH = WGM * WGN * 32;
    constexpr int BK = 32;
    constexpr int KT = 4;
    constexpr int ASTR = 36;
    constexpr int BSTR = BN + 8;
    constexpr int ASZ = BM * ASTR;
    constexpr int BSZ = BK * BSTR;
    constexpr int STG = ASZ + BSZ;
    constexpr int WM = BM / WGM;
    constexpr int WN = BN / WGN;
    constexpr int MT = WM / 16;
    constexpr int NT = WN / 8;

    int zb = blockIdx.z;
    if (MPZ) M = Mptr[zb];
    else if (Mptr) M = *Mptr;
    int bm0 = blockIdx.x * BM;
    if (bm0 >= M) return;
    int bn0 = blockIdx.y * BN;

    const float* Bm = B0 + (ll)zb * sBz;
    const float* bias = bias0 ? bias0 + (ll)zb * sBiasZ : nullptr;
    A += (ll)zb * sAz;
    C += (ll)zb * sCz;
    if (GATHER && MPZ) tok += (ll)zb * TT;

    extern __shared__ float smf[];
    int* toks = (int*)(smf + 3 * STG);
    int tid = threadIdx.x;

    if (GATHER) {
        for (int i = tid; i < BM; i += NTH) {
            int gr = bm0 + i;
            toks[i] = (gr < M) ? tok[gr] : -1;
        }
        __syncthreads();
    }

    int wid = tid >> 5, lane = tid & 31;
    int wm = wid / WGN, wn = wid - wm * WGN;
    int lr = lane >> 2, lc = lane & 3;
    int jmat = lane >> 3, rrow = lane & 7;

    int aoff[MT];
#pragma unroll
    for (int mt = 0; mt < MT; mt++)
        aoff[mt] = (wm * WM + mt * 16 + (jmat & 1) * 8 + rrow) * ASTR + (jmat >> 1) * 4;

    auto fill = [&](int st, int k0) {
        float* As = smf + st * STG;
        float* Bs = As + ASZ;
#pragma unroll
        for (int it = 0; it < BM * 8 / NTH; it++) {
            int i = it * NTH + tid;
            int row = i >> 3, c4 = i & 7;
            float* dst = As + row * ASTR + c4 * 4;
            const float* src;
            int sz = 16;
            if (GATHER) {
                int tk = toks[row];
                src = A + (ll)(tk < 0 ? 0 : tk) * lda + k0 + c4 * 4;
                if (tk < 0) sz = 0;
            } else {
                src = A + (ll)(bm0 + row) * lda + k0 + c4 * 4;
            }
            cpa16(dst, src, sz);
        }
        constexpr int RF4 = BN / 4;
#pragma unroll
        for (int it = 0; it < BK * RF4 / NTH; it++) {
            int i = it * NTH + tid;
            int kk = i / RF4, c4 = i - kk * RF4;
            cpa16(Bs + kk * BSTR + c4 * 4,
                  Bm + (ll)(k0 + kk) * ldb + bn0 + c4 * 4, 16);
        }
    };

    float4 acc[MT][NT];
#pragma unroll
    for (int i = 0; i < MT; i++)
#pragma unroll
        for (int j = 0; j < NT; j++) acc[i][j] = make_float4(0.f, 0.f, 0.f, 0.f);

    int nIt = Kd / BK;
    fill(0, 0);
    asm volatile("cp.async.commit_group;\n");
    if (nIt > 1) {
        fill(1, BK);
        asm volatile("cp.async.commit_group;\n");
    }

    for (int itK = 0; itK < nIt; itK++) {
        if (itK + 1 < nIt) asm volatile("cp.async.wait_group 1;\n");
        else               asm volatile("cp.async.wait_group 0;\n");
        __syncthreads();
        const float* As = smf + (itK % 3) * STG;
        const float* Bs = As + ASZ;
#pragma unroll
        for (int kt = 0; kt < KT; kt++) {
            uint32_t af[MT][4];
            uint32_t bf[NT][2];
#pragma unroll
            for (int mt = 0; mt < MT; mt++)
                ldsm4(af[mt], As + aoff[mt] + kt * 8);
#pragma unroll
            for (int nt = 0; nt < NT; nt++) {
                const float* bp = Bs + (kt * 8 + lc) * BSTR + wn * WN + nt * 8 + lr;
                bf[nt][0] = __float_as_uint(bp[0]);
                bf[nt][1] = __float_as_uint(bp[4 * BSTR]);
            }
#pragma unroll
            for (int mt = 0; mt < MT; mt++)
#pragma unroll
                for (int nt = 0; nt < NT; nt++)
                    mma_tf32(acc[mt][nt], af[mt], bf[nt]);
        }
        if (itK + 2 < nIt) {
            fill((itK + 2) % 3, (itK + 2) * BK);
            asm volatile("cp.async.commit_group;\n");
        }
    }

#pragma unroll
    for (int mt = 0; mt < MT; mt++) {
        int r0 = bm0 + wm * WM + mt * 16 + lr;
        int r1 = r0 + 8;
#pragma unroll
        for (int nt = 0; nt < NT; nt++) {
            int col = bn0 + wn * WN + nt * 8 + lc * 2;
            float v0 = acc[mt][nt].x, v1 = acc[mt][nt].y;
            float v2 = acc[mt][nt].z, v3 = acc[mt][nt].w;
            if (bias) {
                float b0 = bias[col], b1 = bias[col + 1];
                v0 += b0; v1 += b1; v2 += b0; v3 += b1;
            }
            if (EPI == 1) {
                if (r0 < M) {
                    v0 += S[(ll)r0 * ldc + col];
                    v1 += S[(ll)r0 * ldc + col + 1];
                }
                if (r1 < M) {
                    v2 += S[(ll)r1 * ldc + col];
                    v3 += S[(ll)r1 * ldc + col + 1];
                }
            }
            if (r0 < M) {
                C[(ll)r0 * ldc + col] = v0;
                C[(ll)r0 * ldc + col + 1] = v1;
            }
            if (r1 < M) {
                C[(ll)r1 * ldc + col] = v2;
                C[(ll)r1 * ldc + col + 1] = v3;
            }
        }
    }
}

// ================= dual tf32 GEMM: out = silu(A@Wa+ba) * (A@Wb+bb) =================
// BM=64, BN=128, 8 warps (2x4), 256 threads, 2-stage, 2 CTAs/SM.
template<int GATHER, int ZSEL, int MPZ, int VT>
__global__ void __launch_bounds__(256, 2)
tcgd(const float* __restrict__ A, int lda,
     const float* __restrict__ Ba0, const float* __restrict__ Ba1, const float* __restrict__ Ba2,
     const float* __restrict__ Bb0, const float* __restrict__ Bb1, const float* __restrict__ Bb2,
     int ldb, ll sBz,
     const float* __restrict__ ba0, const float* __restrict__ ba1, const float* __restrict__ ba2,
     const float* __restrict__ bb0, const float* __restrict__ bb1, const float* __restrict__ bb2,
     ll sBiasZ,
     float* __restrict__ C, int ldc, ll sCz,
     float* __restrict__ vtout,
     int M, const int* __restrict__ Mptr, int Kd,
     const int* __restrict__ tok) {
    constexpr int NTH = 256;
    constexpr int BM = 64, BN = 128, BK = 32, KT = 4;
    constexpr int ASTR = 36, BSTR = BN + 8;
    constexpr int ASZ = BM * ASTR, BSZ = BK * BSTR;
    constexpr int STG = ASZ + 2 * BSZ;
    constexpr int MT = 2, NT = 4;

    int zb = blockIdx.z;
    if (MPZ) M = Mptr[zb];
    int bm0 = blockIdx.x * BM;
    if (bm0 >= M) return;
    int bn0 = blockIdx.y * BN;

    const float* BA = ZSEL ? (zb == 0 ? Ba0 : (zb == 1 ? Ba1 : Ba2)) : Ba0 + (ll)zb * sBz;
    const float* BBp = ZSEL ? (zb == 0 ? Bb0 : (zb == 1 ? Bb1 : Bb2)) : Bb0 + (ll)zb * sBz;
    const float* biasA = ZSEL ? (zb == 0 ? ba0 : (zb == 1 ? ba1 : ba2)) : ba0 + (ll)zb * sBiasZ;
    const float* biasB = ZSEL ? (zb == 0 ? bb0 : (zb == 1 ? bb1 : bb2)) : bb0 + (ll)zb * sBiasZ;
    C += (ll)zb * sCz;
    if (GATHER && MPZ) tok += (ll)zb * TT;

    extern __shared__ float smf[];
    int* toks = (int*)(smf + 2 * STG);
    int tid = threadIdx.x;

    if (GATHER) {
        for (int i = tid; i < BM; i += NTH) {
            int gr = bm0 + i;
            toks[i] = (gr < M) ? tok[gr] : -1;
        }
        __syncthreads();
    }

    int wid = tid >> 5, lane = tid & 31;
    int wm = wid >> 2, wn = wid & 3;
    int lr = lane >> 2, lc = lane & 3;
    int jmat = lane >> 3, rrow = lane & 7;

    int aoff[MT];
#pragma unroll
    for (int mt = 0; mt < MT; mt++)
        aoff[mt] = (wm * 32 + mt * 16 + (jmat & 1) * 8 + rrow) * ASTR + (jmat >> 1) * 4;

    auto fill = [&](int st, int k0) {
        float* As = smf + st * STG;
        float* Bsa = As + ASZ;
        float* Bsb = Bsa + BSZ;
#pragma unroll
        for (int it = 0; it < BM * 8 / NTH; it++) {
            int i = it * NTH + tid;
            int row = i >> 3, c4 = i & 7;
            float* dst = As + row * ASTR + c4 * 4;
            const float* src;
            int sz = 16;
            if (GATHER) {
                int tk = toks[row];
                src = A + (ll)(tk < 0 ? 0 : tk) * lda + k0 + c4 * 4;
                if (tk < 0) sz = 0;
            } else {
                src = A + (ll)(bm0 + row) * lda + k0 + c4 * 4;
            }
            cpa16(dst, src, sz);
        }
        constexpr int RF4 = BN / 4;
#pragma unroll
        for (int it = 0; it < BK * RF4 / NTH; it++) {
            int i = it * NTH + tid;
            int kk = i / RF4, c4 = i - kk * RF4;
            cpa16(Bsa + kk * BSTR + c4 * 4, BA  + (ll)(k0 + kk) * ldb + bn0 + c4 * 4, 16);
            cpa16(Bsb + kk * BSTR + c4 * 4, BBp + (ll)(k0 + kk) * ldb + bn0 + c4 * 4, 16);
        }
    };

    float4 accA[MT][NT], accB[MT][NT];
#pragma unroll
    for (int i = 0; i < MT; i++)
#pragma unroll
        for (int j = 0; j < NT; j++) {
            accA[i][j] = make_float4(0.f, 0.f, 0.f, 0.f);
            accB[i][j] = make_float4(0.f, 0.f, 0.f, 0.f);
        }

    int nIt = Kd / BK;
    fill(0, 0);
    asm volatile("cp.async.commit_group;\n");

    for (int itK = 0; itK < nIt; itK++) {
        if (itK + 1 < nIt) {
            fill((itK + 1) & 1, (itK + 1) * BK);
            asm volatile("cp.async.commit_group;\n");
            asm volatile("cp.async.wait_group 1;\n");
        } else {
            asm volatile("cp.async.wait_group 0;\n");
        }
        __syncthreads();
        const float* As = smf + (itK & 1) * STG;
        const float* Bsa = As + ASZ;
        const float* Bsb = Bsa + BSZ;
#pragma unroll
        for (int kt = 0; kt < KT; kt++) {
            uint32_t af[MT][4];
#pragma unroll
            for (int mt = 0; mt < MT; mt++)
                ldsm4(af[mt], As + aoff[mt] + kt * 8);
            uint32_t bfa[NT][2], bfb[NT][2];
#pragma unroll
            for (int nt = 0; nt < NT; nt++) {
                int off = (kt * 8 + lc) * BSTR + wn * 32 + nt * 8 + lr;
                bfa[nt][0] = __float_as_uint(Bsa[off]);
                bfa[nt][1] = __float_as_uint(Bsa[off + 4 * BSTR]);
                bfb[nt][0] = __float_as_uint(Bsb[off]);
                bfb[nt][1] = __float_as_uint(Bsb[off + 4 * BSTR]);
            }
#pragma unroll
            for (int mt = 0; mt < MT; mt++)
#pragma unroll
                for (int nt = 0; nt < NT; nt++) {
                    mma_tf32(accA[mt][nt], af[mt], bfa[nt]);
                    mma_tf32(accB[mt][nt], af[mt], bfb[nt]);
                }
        }
        __syncthreads();
    }

#pragma unroll
    for (int mt = 0; mt < MT; mt++) {
        int r0 = bm0 + wm * 32 + mt * 16 + lr;
        int r1 = r0 + 8;
#pragma unroll
        for (int nt = 0; nt < NT; nt++) {
            int col = bn0 + wn * 32 + nt * 8 + lc * 2;
            float ba_ = biasA[col], ba1_ = biasA[col + 1];
            float bb_ = biasB[col], bb1_ = biasB[col + 1];
            float o0 = siluf(accA[mt][nt].x + ba_)  * (accB[mt][nt].x + bb_);
            float o1 = siluf(accA[mt][nt].y + ba1_) * (accB[mt][nt].y + bb1_);
            float o2 = siluf(accA[mt][nt].z + ba_)  * (accB[mt][nt].z + bb_);
            float o3 = siluf(accA[mt][nt].w + ba1_) * (accB[mt][nt].w + bb1_);
            if (VT && zb == 2) {
                int b0 = r0 >> 10, s0 = r0 & 1023;
                int b1 = r1 >> 10, s1 = r1 & 1023;
                vtout[((ll)(b0 * DD + col))     * SS + s0] = o0;
                vtout[((ll)(b0 * DD + col + 1)) * SS + s0] = o1;
                vtout[((ll)(b1 * DD + col))     * SS + s1] = o2;
                vtout[((ll)(b1 * DD + col + 1)) * SS + s1] = o3;
            } else {
                if (r0 < M) {
                    C[(ll)r0 * ldc + col]     = o0;
                    C[(ll)r0 * ldc + col + 1] = o1;
                }
                if (r1 < M) {
                    C[(ll)r1 * ldc + col]     = o2;
                    C[(ll)r1 * ldc + col + 1] = o3;
                }
            }
        }
    }
}

// ================= flash attention: warp-local softmax =================
// 128-row Q tile, 8 warps; warp w owns Q rows [w*16, w*16+16) x ALL 64 keys.
// Softmax stats: shuffle-only. P warp-private (syncwarp). 2 barriers/iter.
#define QSTR 68
__global__ void __launch_bounds__(256, 2)
flash_k(const float* __restrict__ qg, const float* __restrict__ kg,
        const float* __restrict__ vtg, const unsigned* __restrict__ mb,
        float* __restrict__ ctx) {
    extern __shared__ float sm[];
    float* Qs = sm;                         // 128*68 (becomes Ps)
    float* Ks = sm + 128 * QSTR;            // 2 * 64*68
    float* Vs = Ks + 2 * 64 * QSTR;         // 2 * 64*68 (transposed [dk][key])
    float* Ps = Qs;

    int tid = threadIdx.x;
    int z = blockIdx.y;
    int b = z / HH, h = z % HH;
    int q0 = blockIdx.x * 128;
    int lane = tid & 31, wid = tid >> 5;
    int lr = lane >> 2, lc = lane & 3;
    int jmat = lane >> 3, rrow = lane & 7;

    const float* Qg = qg + ((ll)(b * SS + q0)) * DD + h * DK;
#pragma unroll
    for (int it = 0; it < 8; it++) {
        int i = it * 256 + tid;
        int row = i >> 4, c4 = i & 15;
        cpa16(Qs + row * QSTR + c4 * 4, Qg + (ll)row * DD + c4 * 4, 16);
    }
    asm volatile("cp.async.commit_group;\n");

    auto pf = [&](int i) {
        int st = i & 1;
        const float* Kg = kg + ((ll)(b * SS + i * 64)) * DD + h * DK;
        const float* Vg = vtg + ((ll)(b * DD + h * DK)) * SS + i * 64;
#pragma unroll
        for (int it = 0; it < 4; it++) {
            int j = it * 256 + tid;
            int row = j >> 4, c4 = j & 15;
            cpa16(Ks + st * 64 * QSTR + row * QSTR + c4 * 4, Kg + (ll)row * DD + c4 * 4, 16);
        }
#pragma unroll
        for (int it = 0; it < 4; it++) {
            int j = it * 256 + tid;
            int row = j >> 4, c4 = j & 15;    // row = dk
            cpa16(Vs + st * 64 * QSTR + row * QSTR + c4 * 4, Vg + (ll)row * SS + c4 * 4, 16);
        }
    };
    pf(0);
    asm volatile("cp.async.commit_group;\n");

    // Q fragments (register resident)
    asm volatile("cp.async.wait_group 1;\n");
    __syncthreads();
    uint32_t qf[8][4];
    int aoffQ = (wid * 16 + (jmat & 1) * 8 + rrow) * QSTR + (jmat >> 1) * 4;
#pragma unroll
    for (int kt = 0; kt < 8; kt++) ldsm4(qf[kt], Qs + aoffQ + kt * 8);

    float4 oacc[8];
#pragma unroll
    for (int nt = 0; nt < 8; nt++) oacc[nt] = make_float4(0.f, 0.f, 0.f, 0.f);
    float m0 = -1e30f, m1 = -1e30f, l0 = 0.f, l1 = 0.f;
    int r0 = wid * 16 + lr, r1 = r0 + 8;
    const uint2* mp0 = (const uint2*)(mb + ((ll)(b * SS + q0 + r0)) * 32);
    const uint2* mp1 = (const uint2*)(mb + ((ll)(b * SS + q0 + r1)) * 32);

    constexpr int NIT = SS / 64;
    for (int i = 0; i < NIT; i++) {
        if (i + 1 < NIT) {
            pf(i + 1);
            asm volatile("cp.async.commit_group;\n");
            asm volatile("cp.async.wait_group 1;\n");
        } else {
            asm volatile("cp.async.wait_group 0;\n");
        }
        __syncthreads();
        const float* Kst = Ks + (i & 1) * 64 * QSTR;
        const float* Vst = Vs + (i & 1) * 64 * QSTR;

        // S = Q @ K^T   (16 rows x 64 keys per warp)
        float4 s[8];
#pragma unroll
        for (int nt = 0; nt < 8; nt++) s[nt] = make_float4(0.f, 0.f, 0.f, 0.f);
#pragma unroll
        for (int kt = 0; kt < 8; kt++) {
            uint32_t bf[8][2];
#pragma unroll
            for (int p = 0; p < 4; p++) {
                uint32_t t4[4];
                ldsm4(t4, Kst + (p * 16 + (jmat >> 1) * 8 + rrow) * QSTR
                          + (jmat & 1) * 4 + kt * 8);
                bf[2 * p][0] = t4[0]; bf[2 * p][1] = t4[1];
                bf[2 * p + 1][0] = t4[2]; bf[2 * p + 1][1] = t4[3];
            }
#pragma unroll
            for (int nt = 0; nt < 8; nt++) mma_tf32(s[nt], qf[kt], bf[nt]);
        }
        // scale + bitmask (two 32-key words per row)
        uint2 w0 = mp0[i];
        uint2 w1 = mp1[i];
#pragma unroll
        for (int nt = 0; nt < 8; nt++) {
            int bit = (nt & 3) * 8 + lc * 2;
            unsigned u0 = (nt < 4) ? w0.x : w0.y;
            unsigned u1 = (nt < 4) ? w1.x : w1.y;
            s[nt].x = ((u0 >> bit) & 1u)       ? s[nt].x * 0.125f : -1e9f;
            s[nt].y = ((u0 >> (bit + 1)) & 1u) ? s[nt].y * 0.125f : -1e9f;
            s[nt].z = ((u1 >> bit) & 1u)       ? s[nt].z * 0.125f : -1e9f;
            s[nt].w = ((u1 >> (bit + 1)) & 1u) ? s[nt].w * 0.125f : -1e9f;
        }
        // warp-local row max (shuffle over lc group)
        float mx0 = -1e30f, mx1 = -1e30f;
#pragma unroll
        for (int nt = 0; nt < 8; nt++) {
            mx0 = fmaxf(mx0, fmaxf(s[nt].x, s[nt].y));
            mx1 = fmaxf(mx1, fmaxf(s[nt].z, s[nt].w));
        }
#pragma unroll
        for (int o = 1; o <= 2; o <<= 1) {
            mx0 = fmaxf(mx0, __shfl_xor_sync(0xffffffff, mx0, o));
            mx1 = fmaxf(mx1, __shfl_xor_sync(0xffffffff, mx1, o));
        }
        float nm0 = fmaxf(m0, mx0), nm1 = fmaxf(m1, mx1);
        float sc0 = __expf(m0 - nm0), sc1 = __expf(m1 - nm1);
        m0 = nm0; m1 = nm1;
        // exp + store P (warp-private rows) + row sums
        float su0 = 0.f, su1 = 0.f;
#pragma unroll
        for (int nt = 0; nt < 8; nt++) {
            int col = nt * 8 + lc * 2;
            float e0 = __expf(s[nt].x - m0), e1 = __expf(s[nt].y - m0);
            float e2 = __expf(s[nt].z - m1), e3 = __expf(s[nt].w - m1);
            su0 += e0 + e1; su1 += e2 + e3;
            *(float2*)(Ps + r0 * QSTR + col) = make_float2(e0, e1);
            *(float2*)(Ps + r1 * QSTR + col) = make_float2(e2, e3);
        }
#pragma unroll
        for (int o = 1; o <= 2; o <<= 1) {
            su0 += __shfl_xor_sync(0xffffffff, su0, o);
            su1 += __shfl_xor_sync(0xffffffff, su1, o);
        }
        l0 = l0 * sc0 + su0;
        l1 = l1 * sc1 + su1;
#pragma unroll
        for (int nt = 0; nt < 8; nt++) {
            oacc[nt].x *= sc0; oacc[nt].y *= sc0;
            oacc[nt].z *= sc1; oacc[nt].w *= sc1;
        }
        __syncwarp();
        // O += P @ V   (k over 64 keys; V [dk][key] -> ldmatrix)
#pragma unroll
        for (int kt = 0; kt < 8; kt++) {
            uint32_t af[4];
            ldsm4(af, Ps + aoffQ + kt * 8);
            uint32_t bf[8][2];
#pragma unroll
            for (int p = 0; p < 4; p++) {
                uint32_t t4[4];
                ldsm4(t4, Vst + (p * 16 + (jmat >> 1) * 8 + rrow) * QSTR
                          + (jmat & 1) * 4 + kt * 8);
                bf[2 * p][0] = t4[0]; bf[2 * p][1] = t4[1];
                bf[2 * p + 1][0] = t4[2]; bf[2 * p + 1][1] = t4[3];
            }
#pragma unroll
            for (int nt = 0; nt < 8; nt++) mma_tf32(oacc[nt], af, bf[nt]);
        }
        __syncthreads();
    }

    float inv0 = 1.f / l0, inv1 = 1.f / l1;
    float* cg = ctx + ((ll)(b * SS + q0)) * DD + h * DK;
#pragma unroll
    for (int nt = 0; nt < 8; nt++) {
        int col = nt * 8 + lc * 2;
        *(float2*)(cg + (ll)r0 * DD + col) = make_float2(oacc[nt].x * inv0, oacc[nt].y * inv0);
        *(float2*)(cg + (ll)r1 * DD + col) = make_float2(oacc[nt].z * inv1, oacc[nt].w * inv1);
    }
}

// ---------------- gate + routing ----------------
__global__ void zero_counts_k(int* counts) {
    if (threadIdx.x < EE) counts[threadIdx.x] = 0;
}
__global__ void gate_route_k(const float* __restrict__ x2, const float* __restrict__ gw,
                             const float* __restrict__ gb, int* counts, int* etok,
                             int* texp, int* tslot, float* tw) {
    int t = blockIdx.x;
    __shared__ float xs[DD];
    __shared__ float logits[EE];
    const float* row = x2 + (ll)t * DD;
    for (int i = threadIdx.x; i < DD; i += 256) xs[i] = row[i];
    __syncthreads();
    int w = threadIdx.x / 32, lane = threadIdx.x % 32;
    float s = 0.f;
    for (int d = lane; d < DD; d += 32) s += xs[d] * gw[d * EE + w];
    for (int o = 16; o; o >>= 1) s += __shfl_xor_sync(0xffffffff, s, o);
    if (lane == 0) logits[w] = s + gb[w];
    __syncthreads();
    if (threadIdx.x == 0) {
        float p[EE];
        float m = -1e30f;
        for (int e = 0; e < EE; e++) m = fmaxf(m, logits[e]);
        float sum = 0.f;
        for (int e = 0; e < EE; e++) { p[e] = __expf(logits[e] - m); sum += p[e]; }
        for (int e = 0; e < EE; e++) p[e] /= sum;
        int i0 = 0;
        for (int e = 1; e < EE; e++) if (p[e] > p[i0]) i0 = e;
        int i1 = -1;
        for (int e = 0; e < EE; e++) {
            if (e == i0) continue;
            if (i1 < 0 || p[e] > p[i1]) i1 = e;
        }
        float denom = p[i0] + p[i1] + 1e-6f;
        int s0 = atomicAdd(&counts[i0], 1);
        int s1 = atomicAdd(&counts[i1], 1);
        etok[i0 * TT + s0] = t;
        etok[i1 * TT + s1] = t;
        texp[t * 2] = i0; texp[t * 2 + 1] = i1;
        tslot[t * 2] = s0; tslot[t * 2 + 1] = s1;
        tw[t * 2] = p[i0] / denom; tw[t * 2 + 1] = p[i1] / denom;
    }
}

// ---------------- final combine ----------------
__global__ void combine_k(const float* __restrict__ xres, const int* __restrict__ texp,
                          const int* __restrict__ tslot, const float* __restrict__ tw,
                          const float* __restrict__ moe, float* __restrict__ out) {
    int t = blockIdx.x;
    int e0 = texp[t * 2], e1 = texp[t * 2 + 1];
    int s0 = tslot[t * 2], s1 = tslot[t * 2 + 1];
    float w0 = tw[t * 2], w1 = tw[t * 2 + 1];
    const float* m0 = moe + ((size_t)e0 * TT + s0) * DD;
    const float* m1 = moe + ((size_t)e1 * TT + s1) * DD;
    const float* xr = xres + (ll)t * DD;
    float* o = out + (ll)t * DD;
    for (int i = threadIdx.x; i < DD; i += 256)
        o[i] = xr[i] + w0 * m0[i] + w1 * m1[i];
}

// ---------------- host side ----------------
static float* devPtrF(const void* sym) {
    void* p = nullptr;
    cudaGetSymbolAddress(&p, sym);
    return (float*)p;
}
static int* devPtrI(const void* sym) {
    void* p = nullptr;
    cudaGetSymbolAddress(&p, sym);
    return (int*)p;
}

extern "C" void kernel_launch(void* const* d_in, const int* in_sizes, int n_in,
                              void* d_out, int out_size) {
    const float* x    = (const float*)d_in[0];
    const int*   mask = (const int*)  d_in[1];
    const float* wq1 = (const float*)d_in[2];  const float* bq1 = (const float*)d_in[3];
    const float* wq2 = (const float*)d_in[4];  const float* bq2 = (const float*)d_in[5];
    const float* wk1 = (const float*)d_in[6];  const float* bk1 = (const float*)d_in[7];
    const float* wk2 = (const float*)d_in[8];  const float* bk2 = (const float*)d_in[9];
    const float* wv1 = (const float*)d_in[10]; const float* bv1 = (const float*)d_in[11];
    const float* wv2 = (const float*)d_in[12]; const float* bv2 = (const float*)d_in[13];
    const float* wo  = (const float*)d_in[14]; const float* bo  = (const float*)d_in[15];
    const float* ln1g = (const float*)d_in[16]; const float* ln1b = (const float*)d_in[17];
    const float* ln2g = (const float*)d_in[18]; const float* ln2b = (const float*)d_in[19];
    const float* gw  = (const float*)d_in[20]; const float* gb  = (const float*)d_in[21];
    const float* ew1 = (const float*)d_in[22]; const float* eb1 = (const float*)d_in[23];
    const float* ew2 = (const float*)d_in[24]; const float* eb2 = (const float*)d_in[25];
    const float* ew3 = (const float*)d_in[26]; const float* eb3 = (const float*)d_in[27];
    float* out = (float*)d_out;

    float* x2a  = devPtrF(g_x2a);
    float* qkv  = devPtrF(g_qkv);
    float* vt   = devPtrF(g_vt);
    float* ctx  = devPtrF(g_ctx);
    float* xres = devPtrF(g_xres);
    float* x2b  = devPtrF(g_x2b);
    float* emid = devPtrF(g_emid);
    float* moe  = devPtrF(g_moe);
    unsigned* mb = (unsigned*)devPtrI(g_mb);
    int* counts = devPtrI(g_counts);
    int* etok   = devPtrI(g_etok);
    int* texp   = devPtrI(g_texp);
    int* tslot  = devPtrI(g_tslot);
    float* tw   = devPtrF(g_tw);

    float* qb = qkv;
    float* kb = qkv + (ll)TT * DD;

    auto kDP = tcgd<0,1,0,1>;                 // dual proj (ZSEL, VT for z==2)
    auto kDM = tcgd<1,0,1,0>;                 // dual MoE up (gather, per-z)
    auto kO1 = tcg<64,128,2,4,1,0,0>;         // oproj + residual (256 thr, 2 CTA/SM)
    auto kM2 = tcg<64,128,2,4,0,0,1>;         // moe down (per-z)

    int smD  = (2 * (64 * 36 + 2 * 32 * 136) + 64) * 4;     // dual gemm, 2-stage
    int smP  = (3 * (64 * 36 + 32 * (128 + 8))) * 4;        // 64x128 single, 3-stage
    int smFL = (128 * QSTR + 4 * 64 * QSTR) * 4;            // flash 128-row
    cudaFuncSetAttribute(kDP, cudaFuncAttributeMaxDynamicSharedMemorySize, smD);
    cudaFuncSetAttribute(kDM, cudaFuncAttributeMaxDynamicSharedMemorySize, smD);
    cudaFuncSetAttribute(kO1, cudaFuncAttributeMaxDynamicSharedMemorySize, smP);
    cudaFuncSetAttribute(kM2, cudaFuncAttributeMaxDynamicSharedMemorySize, smP);
    cudaFuncSetAttribute(flash_k, cudaFuncAttributeMaxDynamicSharedMemorySize, smFL);

    // 1) LN1 + mask bitpack
    ln_k<<<TT, 256>>>(x, ln1g, ln1b, x2a);
    packmask_k<<<TT / 8, 256>>>(mask, mb);

    // 2) fused SwiGLU projections; z=2 writes V transposed
    kDP<<<dim3(TT/64, DD/128, 3), 256, smD>>>(x2a, DD,
        wq1, wk1, wv1, wq2, wk2, wv2, DD, 0,
        bq1, bk1, bv1, bq2, bk2, bv2, 0,
        qkv, DD, (ll)TT * DD, vt,
        TT, nullptr, DD, nullptr);

    // 3+4) flash attention (128-row Q tiles)
    flash_k<<<dim3(SS / 128, BB * HH), 256, smFL>>>(qb, kb, vt, mb, ctx);

    // 5) out proj + residual
    kO1<<<dim3(TT/64, DD/128, 1), 256, smP>>>(ctx, DD, 0,
        wo, DD, 0, bo, 0, x,
        xres, DD, 0,
        TT, nullptr, DD, nullptr);

    // 6) LN2
    ln_k<<<TT, 256>>>(xres, ln2g, ln2b, x2b);

    // 7) gate + routing
    zero_counts_k<<<1, 32>>>(counts);
    gate_route_k<<<TT, 256>>>(x2b, gw, gb, counts, etok, texp, tslot, tw);

    // 8) MoE: dual up-proj + down-proj, z = expert
    kDM<<<dim3(TT/64, FF/128, EE), 256, smD>>>(x2b, DD,
        ew1, nullptr, nullptr, ew3, nullptr, nullptr, FF, (ll)DD * FF,
        eb1, nullptr, nullptr, eb3, nullptr, nullptr, FF,
        emid, FF, (ll)TT * FF, nullptr,
        0, counts, DD, etok);
    kM2<<<dim3(TT/64, DD/128, EE), 256, smP>>>(emid, FF, (ll)TT * FF,
        ew2, DD, (ll)FF * DD, eb2, DD, nullptr,
        moe, DD, (ll)TT * DD,
        0, counts, FF, nullptr);

    // 9) combine
    combine_k<<<TT, 256>>>(xres, texp, tslot, tw, moe, out);
}

// round 11
// speedup vs baseline: 1.0194x; 1.0194x over previous
#include <cuda_runtime.h>
#include <cuda_bf16.h>
#include <math.h>
#include <stdint.h>

// Problem dims
#define BB 4
#define SS 1024
#define DD 1024
#define FF 2048
#define HH 16
#define EE 8
#define DK 64
#define TT (BB*SS)          // 4096 tokens
typedef long long ll;

// ---------------- static device scratch ----------------
__device__ float g_x2a[TT*DD];
__device__ float g_qkv[3*TT*DD];                // q,k slices (v slice unused)
__device__ float g_vt[TT*DD];                   // V transposed per (b): [b*DD+hd][s]
__device__ float g_ctx[TT*DD];
__device__ float g_xres[TT*DD];
__device__ float g_x2b[TT*DD];
__device__ float g_emid[(size_t)EE*TT*FF];      // MoE mid
__device__ float g_moe[(size_t)EE*TT*DD];
__device__ unsigned g_mb[(size_t)TT*32];        // bitpacked mask: row*32 words
__device__ int   g_counts[EE];
__device__ int   g_etok[EE*TT];
__device__ int   g_texp[TT*2];
__device__ int   g_tslot[TT*2];
__device__ float g_tw[TT*2];

// ---------------- helpers ----------------
__device__ __forceinline__ float blockReduceSum(float v, float* sh) {
    int tid = threadIdx.x;
    sh[tid] = v; __syncthreads();
    for (int s = 128; s > 0; s >>= 1) {
        if (tid < s) sh[tid] += sh[tid + s];
        __syncthreads();
    }
    float r = sh[0]; __syncthreads();
    return r;
}
__device__ __forceinline__ void mma_tf32(float4& d, const uint32_t* a, const uint32_t* b) {
    asm volatile(
        "mma.sync.aligned.m16n8k8.row.col.f32.tf32.tf32.f32 "
        "{%0,%1,%2,%3}, {%4,%5,%6,%7}, {%8,%9}, {%0,%1,%2,%3};"
        : "+f"(d.x), "+f"(d.y), "+f"(d.z), "+f"(d.w)
        : "r"(a[0]), "r"(a[1]), "r"(a[2]), "r"(a[3]), "r"(b[0]), "r"(b[1]));
}
__device__ __forceinline__ void cpa16(float* dst, const float* src, int sz) {
    uint32_t d = (uint32_t)__cvta_generic_to_shared(dst);
    asm volatile("cp.async.cg.shared.global [%0], [%1], 16, %2;\n"
                 :: "r"(d), "l"(src), "r"(sz));
}
__device__ __forceinline__ void ldsm4(uint32_t* d, const float* p) {
    uint32_t a = (uint32_t)__cvta_generic_to_shared(p);
    asm volatile("ldmatrix.sync.aligned.m8n8.x4.shared.b16 {%0,%1,%2,%3}, [%4];"
                 : "=r"(d[0]), "=r"(d[1]), "=r"(d[2]), "=r"(d[3]) : "r"(a));
}
__device__ __forceinline__ float siluf(float x) {
    return x / (1.f + __expf(-x));
}

// ---------------- LayerNorm ----------------
__global__ void ln_k(const float* __restrict__ x, const float* __restrict__ g,
                     const float* __restrict__ b, float* __restrict__ out) {
    __shared__ float sh[256];
    int r = blockIdx.x;
    const float* row = x + (size_t)r * DD;
    float s = 0.f;
    for (int i = threadIdx.x; i < DD; i += 256) s += row[i];
    float mean = blockReduceSum(s, sh) * (1.0f / DD);
    float v = 0.f;
    for (int i = threadIdx.x; i < DD; i += 256) {
        float d = row[i] - mean; v += d * d;
    }
    float var = blockReduceSum(v, sh) * (1.0f / DD);
    float inv = rsqrtf(var + 1e-5f);
    float* o = out + (size_t)r * DD;
    for (int i = threadIdx.x; i < DD; i += 256)
        o[i] = (row[i] - mean) * inv * g[i] + b[i];
}

// ---------------- mask bitpack ----------------
__global__ void packmask_k(const int* __restrict__ mask, unsigned* __restrict__ mb) {
    int wid = threadIdx.x >> 5, lane = threadIdx.x & 31;
    ll row = (ll)blockIdx.x * 8 + wid;
    const int* mrow = mask + row * SS;
#pragma unroll
    for (int w = 0; w < 32; w++) {
        unsigned word = __ballot_sync(0xffffffff, mrow[w * 32 + lane] != 0);
        if (lane == 0) mb[row * 32 + w] = word;
    }
}

// ================= 3-stage pipelined tensor-core tf32 GEMM (single) =================
template<int BM, int BN, int WGM, int WGN, int EPI, int GATHER, int MPZ>
__global__ void __launch_bounds__(WGM*WGN*32, (WGM*WGN*32 == 256) ? 2 : 1)
tcg(const float* __restrict__ A, int lda, ll sAz,
    const float* __restrict__ B0, int ldb, ll sBz,
    const float* __restrict__ bias0, ll sBiasZ,
    const float* __restrict__ S,
    float* __restrict__ C, int ldc, ll sCz,
    int M, const int* __restrict__ Mptr, int Kd,
    const int* __restrict__ tok) {
    constexpr int NTH = WGM * WGN * 32;
    constexpr int BK = 32;
    constexpr int KT = 4;
    constexpr int ASTR = 36;
    constexpr int BSTR = BN + 8;
    constexpr int ASZ = BM * ASTR;
    constexpr int BSZ = BK * BSTR;
    constexpr int STG = ASZ + BSZ;
    constexpr int WM = BM / WGM;
    constexpr int WN = BN / WGN;
    constexpr int MT = WM / 16;
    constexpr int NT = WN / 8;

    int zb = blockIdx.z;
    if (MPZ) M = Mptr[zb];
    else if (Mptr) M = *Mptr;
    int bm0 = blockIdx.x * BM;
    if (bm0 >= M) return;
    int bn0 = blockIdx.y * BN;

    const float* Bm = B0 + (ll)zb * sBz;
    const float* bias = bias0 ? bias0 + (ll)zb * sBiasZ : nullptr;
    A += (ll)zb * sAz;
    C += (ll)zb * sCz;
    if (GATHER && MPZ) tok += (ll)zb * TT;

    extern __shared__ float smf[];
    int* toks = (int*)(smf + 3 * STG);
    int tid = threadIdx.x;

    if (GATHER) {
        for (int i = tid; i < BM; i += NTH) {
            int gr = bm0 + i;
            toks[i] = (gr < M) ? tok[gr] : -1;
        }
        __syncthreads();
    }

    int wid = tid >> 5, lane = tid & 31;
    int wm = wid / WGN, wn = wid - wm * WGN;
    int lr = lane >> 2, lc = lane & 3;
    int jmat = lane >> 3, rrow = lane & 7;

    int aoff[MT];
#pragma unroll
    for (int mt = 0; mt < MT; mt++)
        aoff[mt] = (wm * WM + mt * 16 + (jmat & 1) * 8 + rrow) * ASTR + (jmat >> 1) * 4;

    auto fill = [&](int st, int k0) {
        float* As = smf + st * STG;
        float* Bs = As + ASZ;
#pragma unroll
        for (int it = 0; it < BM * 8 / NTH; it++) {
            int i = it * NTH + tid;
            int row = i >> 3, c4 = i & 7;
            float* dst = As + row * ASTR + c4 * 4;
            const float* src;
            int sz = 16;
            if (GATHER) {
                int tk = toks[row];
                src = A + (ll)(tk < 0 ? 0 : tk) * lda + k0 + c4 * 4;
                if (tk < 0) sz = 0;
            } else {
                src = A + (ll)(bm0 + row) * lda + k0 + c4 * 4;
            }
            cpa16(dst, src, sz);
        }
        constexpr int RF4 = BN / 4;
#pragma unroll
        for (int it = 0; it < BK * RF4 / NTH; it++) {
            int i = it * NTH + tid;
            int kk = i / RF4, c4 = i - kk * RF4;
            cpa16(Bs + kk * BSTR + c4 * 4,
                  Bm + (ll)(k0 + kk) * ldb + bn0 + c4 * 4, 16);
        }
    };

    float4 acc[MT][NT];
#pragma unroll
    for (int i = 0; i < MT; i++)
#pragma unroll
        for (int j = 0; j < NT; j++) acc[i][j] = make_float4(0.f, 0.f, 0.f, 0.f);

    int nIt = Kd / BK;
    fill(0, 0);
    asm volatile("cp.async.commit_group;\n");
    if (nIt > 1) {
        fill(1, BK);
        asm volatile("cp.async.commit_group;\n");
    }

    for (int itK = 0; itK < nIt; itK++) {
        if (itK + 1 < nIt) asm volatile("cp.async.wait_group 1;\n");
        else               asm volatile("cp.async.wait_group 0;\n");
        __syncthreads();
        const float* As = smf + (itK % 3) * STG;
        const float* Bs = As + ASZ;
#pragma unroll
        for (int kt = 0; kt < KT; kt++) {
            uint32_t af[MT][4];
            uint32_t bf[NT][2];
#pragma unroll
            for (int mt = 0; mt < MT; mt++)
                ldsm4(af[mt], As + aoff[mt] + kt * 8);
#pragma unroll
            for (int nt = 0; nt < NT; nt++) {
                const float* bp = Bs + (kt * 8 + lc) * BSTR + wn * WN + nt * 8 + lr;
                bf[nt][0] = __float_as_uint(bp[0]);
                bf[nt][1] = __float_as_uint(bp[4 * BSTR]);
            }
#pragma unroll
            for (int mt = 0; mt < MT; mt++)
#pragma unroll
                for (int nt = 0; nt < NT; nt++)
                    mma_tf32(acc[mt][nt], af[mt], bf[nt]);
        }
        if (itK + 2 < nIt) {
            fill((itK + 2) % 3, (itK + 2) * BK);
            asm volatile("cp.async.commit_group;\n");
        }
    }

#pragma unroll
    for (int mt = 0; mt < MT; mt++) {
        int r0 = bm0 + wm * WM + mt * 16 + lr;
        int r1 = r0 + 8;
#pragma unroll
        for (int nt = 0; nt < NT; nt++) {
            int col = bn0 + wn * WN + nt * 8 + lc * 2;
            float v0 = acc[mt][nt].x, v1 = acc[mt][nt].y;
            float v2 = acc[mt][nt].z, v3 = acc[mt][nt].w;
            if (bias) {
                float b0 = bias[col], b1 = bias[col + 1];
                v0 += b0; v1 += b1; v2 += b0; v3 += b1;
            }
            if (EPI == 1) {
                if (r0 < M) {
                    v0 += S[(ll)r0 * ldc + col];
                    v1 += S[(ll)r0 * ldc + col + 1];
                }
                if (r1 < M) {
                    v2 += S[(ll)r1 * ldc + col];
                    v3 += S[(ll)r1 * ldc + col + 1];
                }
            }
            if (r0 < M) {
                C[(ll)r0 * ldc + col] = v0;
                C[(ll)r0 * ldc + col + 1] = v1;
            }
            if (r1 < M) {
                C[(ll)r1 * ldc + col] = v2;
                C[(ll)r1 * ldc + col + 1] = v3;
            }
        }
    }
}

// ================= dual tf32 GEMM: out = silu(A@Wa+ba) * (A@Wb+bb) =================
// BM=64, BN=128, 8 warps (2x4), 256 threads, 2-stage, 2 CTAs/SM, 1 barrier/iter.
template<int GATHER, int ZSEL, int MPZ, int VT>
__global__ void __launch_bounds__(256, 2)
tcgd(const float* __restrict__ A, int lda,
     const float* __restrict__ Ba0, const float* __restrict__ Ba1, const float* __restrict__ Ba2,
     const float* __restrict__ Bb0, const float* __restrict__ Bb1, const float* __restrict__ Bb2,
     int ldb, ll sBz,
     const float* __restrict__ ba0, const float* __restrict__ ba1, const float* __restrict__ ba2,
     const float* __restrict__ bb0, const float* __restrict__ bb1, const float* __restrict__ bb2,
     ll sBiasZ,
     float* __restrict__ C, int ldc, ll sCz,
     float* __restrict__ vtout,
     int M, const int* __restrict__ Mptr, int Kd,
     const int* __restrict__ tok) {
    constexpr int NTH = 256;
    constexpr int BM = 64, BN = 128, BK = 32, KT = 4;
    constexpr int ASTR = 36, BSTR = BN + 8;
    constexpr int ASZ = BM * ASTR, BSZ = BK * BSTR;
    constexpr int STG = ASZ + 2 * BSZ;
    constexpr int MT = 2, NT = 4;

    int zb = blockIdx.z;
    if (MPZ) M = Mptr[zb];
    int bm0 = blockIdx.x * BM;
    if (bm0 >= M) return;
    int bn0 = blockIdx.y * BN;

    const float* BA = ZSEL ? (zb == 0 ? Ba0 : (zb == 1 ? Ba1 : Ba2)) : Ba0 + (ll)zb * sBz;
    const float* BBp = ZSEL ? (zb == 0 ? Bb0 : (zb == 1 ? Bb1 : Bb2)) : Bb0 + (ll)zb * sBz;
    const float* biasA = ZSEL ? (zb == 0 ? ba0 : (zb == 1 ? ba1 : ba2)) : ba0 + (ll)zb * sBiasZ;
    const float* biasB = ZSEL ? (zb == 0 ? bb0 : (zb == 1 ? bb1 : bb2)) : bb0 + (ll)zb * sBiasZ;
    C += (ll)zb * sCz;
    if (GATHER && MPZ) tok += (ll)zb * TT;

    extern __shared__ float smf[];
    int* toks = (int*)(smf + 2 * STG);
    int tid = threadIdx.x;

    if (GATHER) {
        for (int i = tid; i < BM; i += NTH) {
            int gr = bm0 + i;
            toks[i] = (gr < M) ? tok[gr] : -1;
        }
        __syncthreads();
    }

    int wid = tid >> 5, lane = tid & 31;
    int wm = wid >> 2, wn = wid & 3;
    int lr = lane >> 2, lc = lane & 3;
    int jmat = lane >> 3, rrow = lane & 7;

    int aoff[MT];
#pragma unroll
    for (int mt = 0; mt < MT; mt++)
        aoff[mt] = (wm * 32 + mt * 16 + (jmat & 1) * 8 + rrow) * ASTR + (jmat >> 1) * 4;

    auto fill = [&](int st, int k0) {
        float* As = smf + st * STG;
        float* Bsa = As + ASZ;
        float* Bsb = Bsa + BSZ;
#pragma unroll
        for (int it = 0; it < BM * 8 / NTH; it++) {
            int i = it * NTH + tid;
            int row = i >> 3, c4 = i & 7;
            float* dst = As + row * ASTR + c4 * 4;
            const float* src;
            int sz = 16;
            if (GATHER) {
                int tk = toks[row];
                src = A + (ll)(tk < 0 ? 0 : tk) * lda + k0 + c4 * 4;
                if (tk < 0) sz = 0;
            } else {
                src = A + (ll)(bm0 + row) * lda + k0 + c4 * 4;
            }
            cpa16(dst, src, sz);
        }
        constexpr int RF4 = BN / 4;
#pragma unroll
        for (int it = 0; it < BK * RF4 / NTH; it++) {
            int i = it * NTH + tid;
            int kk = i / RF4, c4 = i - kk * RF4;
            cpa16(Bsa + kk * BSTR + c4 * 4, BA  + (ll)(k0 + kk) * ldb + bn0 + c4 * 4, 16);
            cpa16(Bsb + kk * BSTR + c4 * 4, BBp + (ll)(k0 + kk) * ldb + bn0 + c4 * 4, 16);
        }
    };

    float4 accA[MT][NT], accB[MT][NT];
#pragma unroll
    for (int i = 0; i < MT; i++)
#pragma unroll
        for (int j = 0; j < NT; j++) {
            accA[i][j] = make_float4(0.f, 0.f, 0.f, 0.f);
            accB[i][j] = make_float4(0.f, 0.f, 0.f, 0.f);
        }

    int nIt = Kd / BK;
    fill(0, 0);
    asm volatile("cp.async.commit_group;\n");

    // single barrier per iter: wait(all) -> barrier -> prefetch(next) -> compute
    for (int itK = 0; itK < nIt; itK++) {
        asm volatile("cp.async.wait_group 0;\n");
        __syncthreads();
        if (itK + 1 < nIt) {
            fill((itK + 1) & 1, (itK + 1) * BK);
            asm volatile("cp.async.commit_group;\n");
        }
        const float* As = smf + (itK & 1) * STG;
        const float* Bsa = As + ASZ;
        const float* Bsb = Bsa + BSZ;
#pragma unroll
        for (int kt = 0; kt < KT; kt++) {
            uint32_t af[MT][4];
#pragma unroll
            for (int mt = 0; mt < MT; mt++)
                ldsm4(af[mt], As + aoff[mt] + kt * 8);
            uint32_t bfa[NT][2], bfb[NT][2];
#pragma unroll
            for (int nt = 0; nt < NT; nt++) {
                int off = (kt * 8 + lc) * BSTR + wn * 32 + nt * 8 + lr;
                bfa[nt][0] = __float_as_uint(Bsa[off]);
                bfa[nt][1] = __float_as_uint(Bsa[off + 4 * BSTR]);
                bfb[nt][0] = __float_as_uint(Bsb[off]);
                bfb[nt][1] = __float_as_uint(Bsb[off + 4 * BSTR]);
            }
#pragma unroll
            for (int mt = 0; mt < MT; mt++)
#pragma unroll
                for (int nt = 0; nt < NT; nt++) {
                    mma_tf32(accA[mt][nt], af[mt], bfa[nt]);
                    mma_tf32(accB[mt][nt], af[mt], bfb[nt]);
                }
        }
    }

#pragma unroll
    for (int mt = 0; mt < MT; mt++) {
        int r0 = bm0 + wm * 32 + mt * 16 + lr;
        int r1 = r0 + 8;
#pragma unroll
        for (int nt = 0; nt < NT; nt++) {
            int col = bn0 + wn * 32 + nt * 8 + lc * 2;
            float ba_ = biasA[col], ba1_ = biasA[col + 1];
            float bb_ = biasB[col], bb1_ = biasB[col + 1];
            float o0 = siluf(accA[mt][nt].x + ba_)  * (accB[mt][nt].x + bb_);
            float o1 = siluf(accA[mt][nt].y + ba1_) * (accB[mt][nt].y + bb1_);
            float o2 = siluf(accA[mt][nt].z + ba_)  * (accB[mt][nt].z + bb_);
            float o3 = siluf(accA[mt][nt].w + ba1_) * (accB[mt][nt].w + bb1_);
            if (VT && zb == 2) {
                int b0 = r0 >> 10, s0 = r0 & 1023;
                int b1 = r1 >> 10, s1 = r1 & 1023;
                vtout[((ll)(b0 * DD + col))     * SS + s0] = o0;
                vtout[((ll)(b0 * DD + col + 1)) * SS + s0] = o1;
                vtout[((ll)(b1 * DD + col))     * SS + s1] = o2;
                vtout[((ll)(b1 * DD + col + 1)) * SS + s1] = o3;
            } else {
                if (r0 < M) {
                    C[(ll)r0 * ldc + col]     = o0;
                    C[(ll)r0 * ldc + col + 1] = o1;
                }
                if (r1 < M) {
                    C[(ll)r1 * ldc + col]     = o2;
                    C[(ll)r1 * ldc + col + 1] = o3;
                }
            }
        }
    }
}

// ================= flash attention: warp-local softmax, 1 barrier/iter =================
// 128-row Q tile, 8 warps; warp w owns Q rows [w*16, w*16+16) x ALL 64 keys.
#define QSTR 68
__global__ void __launch_bounds__(256, 2)
flash_k(const float* __restrict__ qg, const float* __restrict__ kg,
        const float* __restrict__ vtg, const unsigned* __restrict__ mb,
        float* __restrict__ ctx) {
    extern __shared__ float sm[];
    float* Qs = sm;                         // 128*68 (becomes Ps)
    float* Ks = sm + 128 * QSTR;            // 2 * 64*68
    float* Vs = Ks + 2 * 64 * QSTR;         // 2 * 64*68 (transposed [dk][key])
    float* Ps = Qs;

    int tid = threadIdx.x;
    int z = blockIdx.y;
    int b = z / HH, h = z % HH;
    int q0 = blockIdx.x * 128;
    int lane = tid & 31, wid = tid >> 5;
    int lr = lane >> 2, lc = lane & 3;
    int jmat = lane >> 3, rrow = lane & 7;

    const float* Qg = qg + ((ll)(b * SS + q0)) * DD + h * DK;
#pragma unroll
    for (int it = 0; it < 8; it++) {
        int i = it * 256 + tid;
        int row = i >> 4, c4 = i & 15;
        cpa16(Qs + row * QSTR + c4 * 4, Qg + (ll)row * DD + c4 * 4, 16);
    }
    asm volatile("cp.async.commit_group;\n");

    auto pf = [&](int i) {
        int st = i & 1;
        const float* Kg = kg + ((ll)(b * SS + i * 64)) * DD + h * DK;
        const float* Vg = vtg + ((ll)(b * DD + h * DK)) * SS + i * 64;
#pragma unroll
        for (int it = 0; it < 4; it++) {
            int j = it * 256 + tid;
            int row = j >> 4, c4 = j & 15;
            cpa16(Ks + st * 64 * QSTR + row * QSTR + c4 * 4, Kg + (ll)row * DD + c4 * 4, 16);
        }
#pragma unroll
        for (int it = 0; it < 4; it++) {
            int j = it * 256 + tid;
            int row = j >> 4, c4 = j & 15;    // row = dk
            cpa16(Vs + st * 64 * QSTR + row * QSTR + c4 * 4, Vg + (ll)row * SS + c4 * 4, 16);
        }
    };
    pf(0);
    asm volatile("cp.async.commit_group;\n");

    // Q fragments (register resident): wait for Q group only
    asm volatile("cp.async.wait_group 1;\n");
    __syncthreads();
    uint32_t qf[8][4];
    int aoffQ = (wid * 16 + (jmat & 1) * 8 + rrow) * QSTR + (jmat >> 1) * 4;
#pragma unroll
    for (int kt = 0; kt < 8; kt++) ldsm4(qf[kt], Qs + aoffQ + kt * 8);

    float4 oacc[8];
#pragma unroll
    for (int nt = 0; nt < 8; nt++) oacc[nt] = make_float4(0.f, 0.f, 0.f, 0.f);
    float m0 = -1e30f, m1 = -1e30f, l0 = 0.f, l1 = 0.f;
    int r0 = wid * 16 + lr, r1 = r0 + 8;
    const uint2* mp0 = (const uint2*)(mb + ((ll)(b * SS + q0 + r0)) * 32);
    const uint2* mp1 = (const uint2*)(mb + ((ll)(b * SS + q0 + r1)) * 32);

    constexpr int NIT = SS / 64;
    for (int i = 0; i < NIT; i++) {
        // wait stage i (only pf(i) outstanding), barrier, then prefetch i+1
        asm volatile("cp.async.wait_group 0;\n");
        __syncthreads();
        if (i + 1 < NIT) {
            pf(i + 1);
            asm volatile("cp.async.commit_group;\n");
        }
        const float* Kst = Ks + (i & 1) * 64 * QSTR;
        const float* Vst = Vs + (i & 1) * 64 * QSTR;

        // S = Q @ K^T   (16 rows x 64 keys per warp)
        float4 s[8];
#pragma unroll
        for (int nt = 0; nt < 8; nt++) s[nt] = make_float4(0.f, 0.f, 0.f, 0.f);
#pragma unroll
        for (int kt = 0; kt < 8; kt++) {
            uint32_t bf[8][2];
#pragma unroll
            for (int p = 0; p < 4; p++) {
                uint32_t t4[4];
                ldsm4(t4, Kst + (p * 16 + (jmat >> 1) * 8 + rrow) * QSTR
                          + (jmat & 1) * 4 + kt * 8);
                bf[2 * p][0] = t4[0]; bf[2 * p][1] = t4[1];
                bf[2 * p + 1][0] = t4[2]; bf[2 * p + 1][1] = t4[3];
            }
#pragma unroll
            for (int nt = 0; nt < 8; nt++) mma_tf32(s[nt], qf[kt], bf[nt]);
        }
        // scale + bitmask (two 32-key words per row)
        uint2 w0 = mp0[i];
        uint2 w1 = mp1[i];
#pragma unroll
        for (int nt = 0; nt < 8; nt++) {
            int bit = (nt & 3) * 8 + lc * 2;
            unsigned u0 = (nt < 4) ? w0.x : w0.y;
            unsigned u1 = (nt < 4) ? w1.x : w1.y;
            s[nt].x = ((u0 >> bit) & 1u)       ? s[nt].x * 0.125f : -1e9f;
            s[nt].y = ((u0 >> (bit + 1)) & 1u) ? s[nt].y * 0.125f : -1e9f;
            s[nt].z = ((u1 >> bit) & 1u)       ? s[nt].z * 0.125f : -1e9f;
            s[nt].w = ((u1 >> (bit + 1)) & 1u) ? s[nt].w * 0.125f : -1e9f;
        }
        // warp-local row max (shuffle over lc group)
        float mx0 = -1e30f, mx1 = -1e30f;
#pragma unroll
        for (int nt = 0; nt < 8; nt++) {
            mx0 = fmaxf(mx0, fmaxf(s[nt].x, s[nt].y));
            mx1 = fmaxf(mx1, fmaxf(s[nt].z, s[nt].w));
        }
#pragma unroll
        for (int o = 1; o <= 2; o <<= 1) {
            mx0 = fmaxf(mx0, __shfl_xor_sync(0xffffffff, mx0, o));
            mx1 = fmaxf(mx1, __shfl_xor_sync(0xffffffff, mx1, o));
        }
        float nm0 = fmaxf(m0, mx0), nm1 = fmaxf(m1, mx1);
        float sc0 = __expf(m0 - nm0), sc1 = __expf(m1 - nm1);
        m0 = nm0; m1 = nm1;
        // exp + store P (warp-private rows) + row sums
        float su0 = 0.f, su1 = 0.f;
#pragma unroll
        for (int nt = 0; nt < 8; nt++) {
            int col = nt * 8 + lc * 2;
            float e0 = __expf(s[nt].x - m0), e1 = __expf(s[nt].y - m0);
            float e2 = __expf(s[nt].z - m1), e3 = __expf(s[nt].w - m1);
            su0 += e0 + e1; su1 += e2 + e3;
            *(float2*)(Ps + r0 * QSTR + col) = make_float2(e0, e1);
            *(float2*)(Ps + r1 * QSTR + col) = make_float2(e2, e3);
        }
#pragma unroll
        for (int o = 1; o <= 2; o <<= 1) {
            su0 += __shfl_xor_sync(0xffffffff, su0, o);
            su1 += __shfl_xor_sync(0xffffffff, su1, o);
        }
        l0 = l0 * sc0 + su0;
        l1 = l1 * sc1 + su1;
#pragma unroll
        for (int nt = 0; nt < 8; nt++) {
            oacc[nt].x *= sc0; oacc[nt].y *= sc0;
            oacc[nt].z *= sc1; oacc[nt].w *= sc1;
        }
        __syncwarp();
        // O += P @ V   (k over 64 keys; V [dk][key] -> ldmatrix)
#pragma unroll
        for (int kt = 0; kt < 8; kt++) {
            uint32_t af[4];
            ldsm4(af, Ps + aoffQ + kt * 8);
            uint32_t bf[8][2];
#pragma unroll
            for (int p = 0; p < 4; p++) {
                uint32_t t4[4];
                ldsm4(t4, Vst + (p * 16 + (jmat >> 1) * 8 + rrow) * QSTR
                          + (jmat & 1) * 4 + kt * 8);
                bf[2 * p][0] = t4[0]; bf[2 * p][1] = t4[1];
                bf[2 * p + 1][0] = t4[2]; bf[2 * p + 1][1] = t4[3];
            }
#pragma unroll
            for (int nt = 0; nt < 8; nt++) mma_tf32(oacc[nt], af, bf[nt]);
        }
    }

    float inv0 = 1.f / l0, inv1 = 1.f / l1;
    float* cg = ctx + ((ll)(b * SS + q0)) * DD + h * DK;
#pragma unroll
    for (int nt = 0; nt < 8; nt++) {
        int col = nt * 8 + lc * 2;
        *(float2*)(cg + (ll)r0 * DD + col) = make_float2(oacc[nt].x * inv0, oacc[nt].y * inv0);
        *(float2*)(cg + (ll)r1 * DD + col) = make_float2(oacc[nt].z * inv1, oacc[nt].w * inv1);
    }
}

// ---------------- gate + routing ----------------
__global__ void zero_counts_k(int* counts) {
    if (threadIdx.x < EE) counts[threadIdx.x] = 0;
}
__global__ void gate_route_k(const float* __restrict__ x2, const float* __restrict__ gw,
                             const float* __restrict__ gb, int* counts, int* etok,
                             int* texp, int* tslot, float* tw) {
    int t = blockIdx.x;
    __shared__ float xs[DD];
    __shared__ float logits[EE];
    const float* row = x2 + (ll)t * DD;
    for (int i = threadIdx.x; i < DD; i += 256) xs[i] = row[i];
    __syncthreads();
    int w = threadIdx.x / 32, lane = threadIdx.x % 32;
    float s = 0.f;
    for (int d = lane; d < DD; d += 32) s += xs[d] * gw[d * EE + w];
    for (int o = 16; o; o >>= 1) s += __shfl_xor_sync(0xffffffff, s, o);
    if (lane == 0) logits[w] = s + gb[w];
    __syncthreads();
    if (threadIdx.x == 0) {
        float p[EE];
        float m = -1e30f;
        for (int e = 0; e < EE; e++) m = fmaxf(m, logits[e]);
        float sum = 0.f;
        for (int e = 0; e < EE; e++) { p[e] = __expf(logits[e] - m); sum += p[e]; }
        for (int e = 0; e < EE; e++) p[e] /= sum;
        int i0 = 0;
        for (int e = 1; e < EE; e++) if (p[e] > p[i0]) i0 = e;
        int i1 = -1;
        for (int e = 0; e < EE; e++) {
            if (e == i0) continue;
            if (i1 < 0 || p[e] > p[i1]) i1 = e;
        }
        float denom = p[i0] + p[i1] + 1e-6f;
        int s0 = atomicAdd(&counts[i0], 1);
        int s1 = atomicAdd(&counts[i1], 1);
        etok[i0 * TT + s0] = t;
        etok[i1 * TT + s1] = t;
        texp[t * 2] = i0; texp[t * 2 + 1] = i1;
        tslot[t * 2] = s0; tslot[t * 2 + 1] = s1;
        tw[t * 2] = p[i0] / denom; tw[t * 2 + 1] = p[i1] / denom;
    }
}

// ---------------- final combine ----------------
__global__ void combine_k(const float* __restrict__ xres, const int* __restrict__ texp,
                          const int* __restrict__ tslot, const float* __restrict__ tw,
                          const float* __restrict__ moe, float* __restrict__ out) {
    int t = blockIdx.x;
    int e0 = texp[t * 2], e1 = texp[t * 2 + 1];
    int s0 = tslot[t * 2], s1 = tslot[t * 2 + 1];
    float w0 = tw[t * 2], w1 = tw[t * 2 + 1];
    const float* m0 = moe + ((size_t)e0 * TT + s0) * DD;
    const float* m1 = moe + ((size_t)e1 * TT + s1) * DD;
    const float* xr = xres + (ll)t * DD;
    float* o = out + (ll)t * DD;
    for (int i = threadIdx.x; i < DD; i += 256)
        o[i] = xr[i] + w0 * m0[i] + w1 * m1[i];
}

// ---------------- host side ----------------
static float* devPtrF(const void* sym) {
    void* p = nullptr;
    cudaGetSymbolAddress(&p, sym);
    return (float*)p;
}
static int* devPtrI(const void* sym) {
    void* p = nullptr;
    cudaGetSymbolAddress(&p, sym);
    return (int*)p;
}

extern "C" void kernel_launch(void* const* d_in, const int* in_sizes, int n_in,
                              void* d_out, int out_size) {
    const float* x    = (const float*)d_in[0];
    const int*   mask = (const int*)  d_in[1];
    const float* wq1 = (const float*)d_in[2];  const float* bq1 = (const float*)d_in[3];
    const float* wq2 = (const float*)d_in[4];  const float* bq2 = (const float*)d_in[5];
    const float* wk1 = (const float*)d_in[6];  const float* bk1 = (const float*)d_in[7];
    const float* wk2 = (const float*)d_in[8];  const float* bk2 = (const float*)d_in[9];
    const float* wv1 = (const float*)d_in[10]; const float* bv1 = (const float*)d_in[11];
    const float* wv2 = (const float*)d_in[12]; const float* bv2 = (const float*)d_in[13];
    const float* wo  = (const float*)d_in[14]; const float* bo  = (const float*)d_in[15];
    const float* ln1g = (const float*)d_in[16]; const float* ln1b = (const float*)d_in[17];
    const float* ln2g = (const float*)d_in[18]; const float* ln2b = (const float*)d_in[19];
    const float* gw  = (const float*)d_in[20]; const float* gb  = (const float*)d_in[21];
    const float* ew1 = (const float*)d_in[22]; const float* eb1 = (const float*)d_in[23];
    const float* ew2 = (const float*)d_in[24]; const float* eb2 = (const float*)d_in[25];
    const float* ew3 = (const float*)d_in[26]; const float* eb3 = (const float*)d_in[27];
    float* out = (float*)d_out;

    float* x2a  = devPtrF(g_x2a);
    float* qkv  = devPtrF(g_qkv);
    float* vt   = devPtrF(g_vt);
    float* ctx  = devPtrF(g_ctx);
    float* xres = devPtrF(g_xres);
    float* x2b  = devPtrF(g_x2b);
    float* emid = devPtrF(g_emid);
    float* moe  = devPtrF(g_moe);
    unsigned* mb = (unsigned*)devPtrI(g_mb);
    int* counts = devPtrI(g_counts);
    int* etok   = devPtrI(g_etok);
    int* texp   = devPtrI(g_texp);
    int* tslot  = devPtrI(g_tslot);
    float* tw   = devPtrF(g_tw);

    float* qb = qkv;
    float* kb = qkv + (ll)TT * DD;

    auto kDP = tcgd<0,1,0,1>;                 // dual proj (ZSEL, VT for z==2)
    auto kDM = tcgd<1,0,1,0>;                 // dual MoE up (gather, per-z)
    auto kO1 = tcg<128,256,2,8,1,0,0>;        // oproj + residual (512 thr)
    auto kM2 = tcg<128,256,2,8,0,0,1>;        // moe down (per-z, 512 thr)

    int smD  = (2 * (64 * 36 + 2 * 32 * 136) + 64) * 4;     // dual gemm, 2-stage
    int smP  = (3 * (128 * 36 + 32 * (256 + 8))) * 4;       // 128x256 single, 3-stage
    int smFL = (128 * QSTR + 4 * 64 * QSTR) * 4;            // flash 128-row
    cudaFuncSetAttribute(kDP, cudaFuncAttributeMaxDynamicSharedMemorySize, smD);
    cudaFuncSetAttribute(kDM, cudaFuncAttributeMaxDynamicSharedMemorySize, smD);
    cudaFuncSetAttribute(kO1, cudaFuncAttributeMaxDynamicSharedMemorySize, smP);
    cudaFuncSetAttribute(kM2, cudaFuncAttributeMaxDynamicSharedMemorySize, smP);
    cudaFuncSetAttribute(flash_k, cudaFuncAttributeMaxDynamicSharedMemorySize, smFL);

    // 1) LN1 + mask bitpack
    ln_k<<<TT, 256>>>(x, ln1g, ln1b, x2a);
    packmask_k<<<TT / 8, 256>>>(mask, mb);

    // 2) fused SwiGLU projections; z=2 writes V transposed
    kDP<<<dim3(TT/64, DD/128, 3), 256, smD>>>(x2a, DD,
        wq1, wk1, wv1, wq2, wk2, wv2, DD, 0,
        bq1, bk1, bv1, bq2, bk2, bv2, 0,
        qkv, DD, (ll)TT * DD, vt,
        TT, nullptr, DD, nullptr);

    // 3+4) flash attention (128-row Q tiles)
    flash_k<<<dim3(SS / 128, BB * HH), 256, smFL>>>(qb, kb, vt, mb, ctx);

    // 5) out proj + residual
    kO1<<<dim3(TT/128, DD/256, 1), 512, smP>>>(ctx, DD, 0,
        wo, DD, 0, bo, 0, x,
        xres, DD, 0,
        TT, nullptr, DD, nullptr);

    // 6) LN2
    ln_k<<<TT, 256>>>(xres, ln2g, ln2b, x2b);

    // 7) gate + routing
    zero_counts_k<<<1, 32>>>(counts);
    gate_route_k<<<TT, 256>>>(x2b, gw, gb, counts, etok, texp, tslot, tw);

    // 8) MoE: dual up-proj + down-proj, z = expert
    kDM<<<dim3(TT/64, FF/128, EE), 256, smD>>>(x2b, DD,
        ew1, nullptr, nullptr, ew3, nullptr, nullptr, FF, (ll)DD * FF,
        eb1, nullptr, nullptr, eb3, nullptr, nullptr, FF,
        emid, FF, (ll)TT * FF, nullptr,
        0, counts, DD, etok);
    kM2<<<dim3(TT/128, DD/256, EE), 512, smP>>>(emid, FF, (ll)TT * FF,
        ew2, DD, (ll)FF * DD, eb2, DD, nullptr,
        moe, DD, (ll)TT * DD,
        0, counts, FF, nullptr);

    // 9) combine
    combine_k<<<TT, 256>>>(xres, texp, tslot, tw, moe, out);
}

// round 12
// speedup vs baseline: 1.4930x; 1.4647x over previous
#include <cuda_runtime.h>
#include <cuda_fp16.h>
#include <math.h>
#include <stdint.h>

// Problem dims
#define BB 4
#define SS 1024
#define DD 1024
#define FF 2048
#define HH 16
#define EE 8
#define DK 64
#define TT (BB*SS)          // 4096 tokens
typedef long long ll;

// fp16 weight scratch offsets (halves)
#define WP (DD*DD)
#define OFF_Q1 0
#define OFF_Q2 (1*WP)
#define OFF_K1 (2*WP)
#define OFF_K2 (3*WP)
#define OFF_V1 (4*WP)
#define OFF_V2 (5*WP)
#define OFF_WO (6*WP)
#define OFF_E1 (7*WP)
#define OFF_E3 (OFF_E1 + (ll)EE*DD*FF)
#define OFF_E2 (OFF_E3 + (ll)EE*DD*FF)
#define HW_TOTAL (OFF_E2 + (ll)EE*FF*DD)

// ---------------- static device scratch ----------------
__device__ __half g_hw[HW_TOTAL];               // fp16 weights (~115MB)
__device__ __half g_hx2a[TT*DD];
__device__ __half g_hqk[2*TT*DD];               // q,k fp16
__device__ __half g_hvt[TT*DD];                 // V transposed fp16: [b*DD+hd][s]
__device__ __half g_hctx[TT*DD];
__device__ __half g_hx2b[TT*DD];
__device__ __half g_hemid[(size_t)EE*TT*FF];    // MoE mid fp16 (67MB)
__device__ float g_x2b[TT*DD];                  // fp32 copy for gate
__device__ float g_xres[TT*DD];
__device__ float g_moe[(size_t)EE*TT*DD];
__device__ unsigned g_mb[(size_t)TT*32];
__device__ int   g_counts[EE];
__device__ int   g_etok[EE*TT];
__device__ int   g_texp[TT*2];
__device__ int   g_tslot[TT*2];
__device__ float g_tw[TT*2];

// ---------------- helpers ----------------
__device__ __forceinline__ float blockReduceSum(float v, float* sh) {
    int tid = threadIdx.x;
    sh[tid] = v; __syncthreads();
    for (int s = 128; s > 0; s >>= 1) {
        if (tid < s) sh[tid] += sh[tid + s];
        __syncthreads();
    }
    float r = sh[0]; __syncthreads();
    return r;
}
__device__ __forceinline__ void mma16(float4& d, const uint32_t* a, const uint32_t* b) {
    asm volatile(
        "mma.sync.aligned.m16n8k16.row.col.f32.f16.f16.f32 "
        "{%0,%1,%2,%3}, {%4,%5,%6,%7}, {%8,%9}, {%0,%1,%2,%3};"
        : "+f"(d.x), "+f"(d.y), "+f"(d.z), "+f"(d.w)
        : "r"(a[0]), "r"(a[1]), "r"(a[2]), "r"(a[3]), "r"(b[0]), "r"(b[1]));
}
__device__ __forceinline__ void cpa16(void* dst, const void* src, int sz) {
    uint32_t d = (uint32_t)__cvta_generic_to_shared(dst);
    asm volatile("cp.async.cg.shared.global [%0], [%1], 16, %2;\n"
                 :: "r"(d), "l"(src), "r"(sz));
}
__device__ __forceinline__ void ldsm4(uint32_t* d, const __half* p) {
    uint32_t a = (uint32_t)__cvta_generic_to_shared(p);
    asm volatile("ldmatrix.sync.aligned.m8n8.x4.shared.b16 {%0,%1,%2,%3}, [%4];"
                 : "=r"(d[0]), "=r"(d[1]), "=r"(d[2]), "=r"(d[3]) : "r"(a));
}
__device__ __forceinline__ void ldsm4t(uint32_t* d, const __half* p) {
    uint32_t a = (uint32_t)__cvta_generic_to_shared(p);
    asm volatile("ldmatrix.sync.aligned.m8n8.x4.trans.shared.b16 {%0,%1,%2,%3}, [%4];"
                 : "=r"(d[0]), "=r"(d[1]), "=r"(d[2]), "=r"(d[3]) : "r"(a));
}
__device__ __forceinline__ float siluf(float x) {
    return x / (1.f + __expf(-x));
}

// ---------------- fp32 -> fp16 convert ----------------
__global__ void cvt_k(const float* __restrict__ s, __half* __restrict__ d, ll n) {
    ll i = ((ll)blockIdx.x * 256 + threadIdx.x) * 4;
    if (i < n) {
        float4 v = *(const float4*)(s + i);
        __half2* d2 = (__half2*)(d + i);
        d2[0] = __floats2half2_rn(v.x, v.y);
        d2[1] = __floats2half2_rn(v.z, v.w);
    }
}

// ---------------- LayerNorm (fp16 out, optional fp32 out) ----------------
__global__ void ln_k(const float* __restrict__ x, const float* __restrict__ g,
                     const float* __restrict__ b, __half* __restrict__ out16,
                     float* __restrict__ out32) {
    __shared__ float sh[256];
    int r = blockIdx.x;
    const float* row = x + (size_t)r * DD;
    float s = 0.f;
    for (int i = threadIdx.x; i < DD; i += 256) s += row[i];
    float mean = blockReduceSum(s, sh) * (1.0f / DD);
    float v = 0.f;
    for (int i = threadIdx.x; i < DD; i += 256) {
        float d = row[i] - mean; v += d * d;
    }
    float var = blockReduceSum(v, sh) * (1.0f / DD);
    float inv = rsqrtf(var + 1e-5f);
    for (int i = threadIdx.x; i < DD; i += 256) {
        float val = (row[i] - mean) * inv * g[i] + b[i];
        out16[(size_t)r * DD + i] = __float2half(val);
        if (out32) out32[(size_t)r * DD + i] = val;
    }
}

// ---------------- mask bitpack ----------------
__global__ void packmask_k(const int* __restrict__ mask, unsigned* __restrict__ mb) {
    int wid = threadIdx.x >> 5, lane = threadIdx.x & 31;
    ll row = (ll)blockIdx.x * 8 + wid;
    const int* mrow = mask + row * SS;
#pragma unroll
    for (int w = 0; w < 32; w++) {
        unsigned word = __ballot_sync(0xffffffff, mrow[w * 32 + lane] != 0);
        if (lane == 0) mb[row * 32 + w] = word;
    }
}

// ================= fp16 tensor-core GEMM (single, 3-stage) =================
// A [M,K] fp16 row-major; B [K,N] fp16 K-major (ldsm.trans); C fp32.
// EPI: 0 = +bias; 1 = +bias + S residual (fp32).
template<int BM, int BN, int WGM, int WGN, int EPI, int GATHER, int MPZ>
__global__ void __launch_bounds__(WGM*WGN*32)
tcg(const __half* __restrict__ A, int lda, ll sAz,
    const __half* __restrict__ B0, int ldb, ll sBz,
    const float* __restrict__ bias0, ll sBiasZ,
    const float* __restrict__ S,
    float* __restrict__ C, int ldc, ll sCz,
    int M, const int* __restrict__ Mptr, int Kd,
    const int* __restrict__ tok) {
    constexpr int NTH = WGM * WGN * 32;
    constexpr int BK = 32;
    constexpr int ASTR = BK + 8;            // halves
    constexpr int BSTR = BN + 8;
    constexpr int ASZ = BM * ASTR;
    constexpr int BSZ = BK * BSTR;
    constexpr int STG = ASZ + BSZ;
    constexpr int WM = BM / WGM;
    constexpr int WN = BN / WGN;
    constexpr int MT = WM / 16;
    constexpr int NT = WN / 8;

    int zb = blockIdx.z;
    if (MPZ) M = Mptr[zb];
    else if (Mptr) M = *Mptr;
    int bm0 = blockIdx.x * BM;
    if (bm0 >= M) return;
    int bn0 = blockIdx.y * BN;

    const __half* Bm = B0 + (ll)zb * sBz;
    const float* bias = bias0 ? bias0 + (ll)zb * sBiasZ : nullptr;
    A += (ll)zb * sAz;
    C += (ll)zb * sCz;
    if (GATHER && MPZ) tok += (ll)zb * TT;

    extern __shared__ __half smh[];
    int* toks = (int*)(smh + 3 * STG);
    int tid = threadIdx.x;

    if (GATHER) {
        for (int i = tid; i < BM; i += NTH) {
            int gr = bm0 + i;
            toks[i] = (gr < M) ? tok[gr] : -1;
        }
        __syncthreads();
    }

    int wid = tid >> 5, lane = tid & 31;
    int wm = wid / WGN, wn = wid - wm * WGN;
    int lr = lane >> 2, lc = lane & 3;

    int aoffA[MT];
#pragma unroll
    for (int mt = 0; mt < MT; mt++)
        aoffA[mt] = (wm * WM + mt * 16 + (lane & 15)) * ASTR + (lane >> 4) * 8;
    int krow = (lane & 7) + ((lane >> 3) & 1) * 8;
    int ncol = (lane >> 4) * 8;

    auto fill = [&](int st, int k0) {
        __half* As = smh + st * STG;
        __half* Bs = As + ASZ;
        // A: BM rows x 32 halves = 4 chunks/row
#pragma unroll
        for (int it = 0; it < BM * 4 / NTH; it++) {
            int i = it * NTH + tid;
            int row = i >> 2, c8 = i & 3;
            __half* dst = As + row * ASTR + c8 * 8;
            const __half* src;
            int sz = 16;
            if (GATHER) {
                int tk = toks[row];
                src = A + (ll)(tk < 0 ? 0 : tk) * lda + k0 + c8 * 8;
                if (tk < 0) sz = 0;
            } else {
                src = A + (ll)(bm0 + row) * lda + k0 + c8 * 8;
            }
            cpa16(dst, src, sz);
        }
        constexpr int RC = BN / 8;  // chunks per k-row
#pragma unroll
        for (int it = 0; it < BK * RC / NTH; it++) {
            int i = it * NTH + tid;
            int kk = i / RC, c8 = i - kk * RC;
            cpa16(Bs + kk * BSTR + c8 * 8,
                  Bm + (ll)(k0 + kk) * ldb + bn0 + c8 * 8, 16);
        }
    };

    float4 acc[MT][NT];
#pragma unroll
    for (int i = 0; i < MT; i++)
#pragma unroll
        for (int j = 0; j < NT; j++) acc[i][j] = make_float4(0.f, 0.f, 0.f, 0.f);

    int nIt = Kd / BK;
    fill(0, 0);
    asm volatile("cp.async.commit_group;\n");
    if (nIt > 1) {
        fill(1, BK);
        asm volatile("cp.async.commit_group;\n");
    }

    for (int itK = 0; itK < nIt; itK++) {
        if (itK + 1 < nIt) asm volatile("cp.async.wait_group 1;\n");
        else               asm volatile("cp.async.wait_group 0;\n");
        __syncthreads();
        const __half* As = smh + (itK % 3) * STG;
        const __half* Bs = As + ASZ;
#pragma unroll
        for (int ks = 0; ks < 2; ks++) {
            uint32_t af[MT][4];
#pragma unroll
            for (int mt = 0; mt < MT; mt++)
                ldsm4(af[mt], As + aoffA[mt] + ks * 16);
            uint32_t bf[NT][2];
#pragma unroll
            for (int np = 0; np < NT / 2; np++) {
                uint32_t t4[4];
                ldsm4t(t4, Bs + (ks * 16 + krow) * BSTR + wn * WN + np * 16 + ncol);
                bf[2 * np][0] = t4[0]; bf[2 * np][1] = t4[1];
                bf[2 * np + 1][0] = t4[2]; bf[2 * np + 1][1] = t4[3];
            }
#pragma unroll
            for (int mt = 0; mt < MT; mt++)
#pragma unroll
                for (int nt = 0; nt < NT; nt++)
                    mma16(acc[mt][nt], af[mt], bf[nt]);
        }
        if (itK + 2 < nIt) {
            fill((itK + 2) % 3, (itK + 2) * BK);
            asm volatile("cp.async.commit_group;\n");
        }
    }

#pragma unroll
    for (int mt = 0; mt < MT; mt++) {
        int r0 = bm0 + wm * WM + mt * 16 + lr;
        int r1 = r0 + 8;
#pragma unroll
        for (int nt = 0; nt < NT; nt++) {
            int col = bn0 + wn * WN + nt * 8 + lc * 2;
            float v0 = acc[mt][nt].x, v1 = acc[mt][nt].y;
            float v2 = acc[mt][nt].z, v3 = acc[mt][nt].w;
            if (bias) {
                float b0 = bias[col], b1 = bias[col + 1];
                v0 += b0; v1 += b1; v2 += b0; v3 += b1;
            }
            if (EPI == 1) {
                if (r0 < M) {
                    v0 += S[(ll)r0 * ldc + col];
                    v1 += S[(ll)r0 * ldc + col + 1];
                }
                if (r1 < M) {
                    v2 += S[(ll)r1 * ldc + col];
                    v3 += S[(ll)r1 * ldc + col + 1];
                }
            }
            if (r0 < M) {
                C[(ll)r0 * ldc + col] = v0;
                C[(ll)r0 * ldc + col + 1] = v1;
            }
            if (r1 < M) {
                C[(ll)r1 * ldc + col] = v2;
                C[(ll)r1 * ldc + col + 1] = v3;
            }
        }
    }
}

// ================= fp16 dual GEMM: out = silu(A@Wa+ba)*(A@Wb+bb), fp16 out =================
// BM=64, BN=128, 8 warps (2x4), 256 thr, 2-stage, 1 barrier/iter, 2 CTAs/SM.
template<int GATHER, int ZSEL, int MPZ, int VT>
__global__ void __launch_bounds__(256, 2)
tcgd(const __half* __restrict__ A, int lda,
     const __half* __restrict__ Ba0, const __half* __restrict__ Ba1, const __half* __restrict__ Ba2,
     const __half* __restrict__ Bb0, const __half* __restrict__ Bb1, const __half* __restrict__ Bb2,
     int ldb, ll sBz,
     const float* __restrict__ ba0, const float* __restrict__ ba1, const float* __restrict__ ba2,
     const float* __restrict__ bb0, const float* __restrict__ bb1, const float* __restrict__ bb2,
     ll sBiasZ,
     __half* __restrict__ C, int ldc, ll sCz,
     __half* __restrict__ vtout,
     int M, const int* __restrict__ Mptr, int Kd,
     const int* __restrict__ tok) {
    constexpr int NTH = 256;
    constexpr int BM = 64, BN = 128, BK = 32;
    constexpr int ASTR = 40, BSTR = BN + 8;
    constexpr int ASZ = BM * ASTR, BSZ = BK * BSTR;
    constexpr int STG = ASZ + 2 * BSZ;
    constexpr int MT = 2, NT = 4;

    int zb = blockIdx.z;
    if (MPZ) M = Mptr[zb];
    int bm0 = blockIdx.x * BM;
    if (bm0 >= M) return;
    int bn0 = blockIdx.y * BN;

    const __half* BA = ZSEL ? (zb == 0 ? Ba0 : (zb == 1 ? Ba1 : Ba2)) : Ba0 + (ll)zb * sBz;
    const __half* BBp = ZSEL ? (zb == 0 ? Bb0 : (zb == 1 ? Bb1 : Bb2)) : Bb0 + (ll)zb * sBz;
    const float* biasA = ZSEL ? (zb == 0 ? ba0 : (zb == 1 ? ba1 : ba2)) : ba0 + (ll)zb * sBiasZ;
    const float* biasB = ZSEL ? (zb == 0 ? bb0 : (zb == 1 ? bb1 : bb2)) : bb0 + (ll)zb * sBiasZ;
    C += (ll)zb * sCz;
    if (GATHER && MPZ) tok += (ll)zb * TT;

    extern __shared__ __half smh[];
    int* toks = (int*)(smh + 2 * STG);
    int tid = threadIdx.x;

    if (GATHER) {
        for (int i = tid; i < BM; i += NTH) {
            int gr = bm0 + i;
            toks[i] = (gr < M) ? tok[gr] : -1;
        }
        __syncthreads();
    }

    int wid = tid >> 5, lane = tid & 31;
    int wm = wid >> 2, wn = wid & 3;
    int lr = lane >> 2, lc = lane & 3;

    int aoffA[MT];
#pragma unroll
    for (int mt = 0; mt < MT; mt++)
        aoffA[mt] = (wm * 32 + mt * 16 + (lane & 15)) * ASTR + (lane >> 4) * 8;
    int krow = (lane & 7) + ((lane >> 3) & 1) * 8;
    int ncol = (lane >> 4) * 8;

    auto fill = [&](int st, int k0) {
        __half* As = smh + st * STG;
        __half* Bsa = As + ASZ;
        __half* Bsb = Bsa + BSZ;
#pragma unroll
        for (int it = 0; it < BM * 4 / NTH; it++) {
            int i = it * NTH + tid;
            int row = i >> 2, c8 = i & 3;
            __half* dst = As + row * ASTR + c8 * 8;
            const __half* src;
            int sz = 16;
            if (GATHER) {
                int tk = toks[row];
                src = A + (ll)(tk < 0 ? 0 : tk) * lda + k0 + c8 * 8;
                if (tk < 0) sz = 0;
            } else {
                src = A + (ll)(bm0 + row) * lda + k0 + c8 * 8;
            }
            cpa16(dst, src, sz);
        }
        constexpr int RC = BN / 8;  // 16
#pragma unroll
        for (int it = 0; it < BK * RC / NTH; it++) {
            int i = it * NTH + tid;
            int kk = i >> 4, c8 = i & 15;
            cpa16(Bsa + kk * BSTR + c8 * 8, BA  + (ll)(k0 + kk) * ldb + bn0 + c8 * 8, 16);
            cpa16(Bsb + kk * BSTR + c8 * 8, BBp + (ll)(k0 + kk) * ldb + bn0 + c8 * 8, 16);
        }
    };

    float4 accA[MT][NT], accB[MT][NT];
#pragma unroll
    for (int i = 0; i < MT; i++)
#pragma unroll
        for (int j = 0; j < NT; j++) {
            accA[i][j] = make_float4(0.f, 0.f, 0.f, 0.f);
            accB[i][j] = make_float4(0.f, 0.f, 0.f, 0.f);
        }

    int nIt = Kd / BK;
    fill(0, 0);
    asm volatile("cp.async.commit_group;\n");

    for (int itK = 0; itK < nIt; itK++) {
        asm volatile("cp.async.wait_group 0;\n");
        __syncthreads();
        if (itK + 1 < nIt) {
            fill((itK + 1) & 1, (itK + 1) * BK);
            asm volatile("cp.async.commit_group;\n");
        }
        const __half* As = smh + (itK & 1) * STG;
        const __half* Bsa = As + ASZ;
        const __half* Bsb = Bsa + BSZ;
#pragma unroll
        for (int ks = 0; ks < 2; ks++) {
            uint32_t af[MT][4];
#pragma unroll
            for (int mt = 0; mt < MT; mt++)
                ldsm4(af[mt], As + aoffA[mt] + ks * 16);
            uint32_t bfa[NT][2], bfb[NT][2];
#pragma unroll
            for (int np = 0; np < 2; np++) {
                uint32_t t4[4];
                ldsm4t(t4, Bsa + (ks * 16 + krow) * BSTR + wn * 32 + np * 16 + ncol);
                bfa[2 * np][0] = t4[0]; bfa[2 * np][1] = t4[1];
                bfa[2 * np + 1][0] = t4[2]; bfa[2 * np + 1][1] = t4[3];
                ldsm4t(t4, Bsb + (ks * 16 + krow) * BSTR + wn * 32 + np * 16 + ncol);
                bfb[2 * np][0] = t4[0]; bfb[2 * np][1] = t4[1];
                bfb[2 * np + 1][0] = t4[2]; bfb[2 * np + 1][1] = t4[3];
            }
#pragma unroll
            for (int mt = 0; mt < MT; mt++)
#pragma unroll
                for (int nt = 0; nt < NT; nt++) {
                    mma16(accA[mt][nt], af[mt], bfa[nt]);
                    mma16(accB[mt][nt], af[mt], bfb[nt]);
                }
        }
    }

#pragma unroll
    for (int mt = 0; mt < MT; mt++) {
        int r0 = bm0 + wm * 32 + mt * 16 + lr;
        int r1 = r0 + 8;
#pragma unroll
        for (int nt = 0; nt < NT; nt++) {
            int col = bn0 + wn * 32 + nt * 8 + lc * 2;
            float ba_ = biasA[col], ba1_ = biasA[col + 1];
            float bb_ = biasB[col], bb1_ = biasB[col + 1];
            float o0 = siluf(accA[mt][nt].x + ba_)  * (accB[mt][nt].x + bb_);
            float o1 = siluf(accA[mt][nt].y + ba1_) * (accB[mt][nt].y + bb1_);
            float o2 = siluf(accA[mt][nt].z + ba_)  * (accB[mt][nt].z + bb_);
            float o3 = siluf(accA[mt][nt].w + ba1_) * (accB[mt][nt].w + bb1_);
            if (VT && zb == 2) {
                int b0 = r0 >> 10, s0 = r0 & 1023;
                int b1 = r1 >> 10, s1 = r1 & 1023;
                vtout[((ll)(b0 * DD + col))     * SS + s0] = __float2half(o0);
                vtout[((ll)(b0 * DD + col + 1)) * SS + s0] = __float2half(o1);
                vtout[((ll)(b1 * DD + col))     * SS + s1] = __float2half(o2);
                vtout[((ll)(b1 * DD + col + 1)) * SS + s1] = __float2half(o3);
            } else {
                if (r0 < M)
                    *(__half2*)(C + (ll)r0 * ldc + col) = __floats2half2_rn(o0, o1);
                if (r1 < M)
                    *(__half2*)(C + (ll)r1 * ldc + col) = __floats2half2_rn(o2, o3);
            }
        }
    }
}

// ================= flash attention (fp16, warp-local softmax) =================
// 128-row Q tile, 8 warps; warp w owns 16 Q rows x all 64 keys. 1 barrier/iter.
#define QSH 72
__global__ void __launch_bounds__(256, 2)
flash_k(const __half* __restrict__ qg, const __half* __restrict__ kg,
        const __half* __restrict__ vtg, const unsigned* __restrict__ mb,
        __half* __restrict__ ctx) {
    extern __shared__ __half smh[];
    __half* Qs = smh;                       // 128*72 (becomes Ps)
    __half* Ks = smh + 128 * QSH;           // 2 * 64*72
    __half* Vs = Ks + 2 * 64 * QSH;         // 2 * 64*72 ([dk][key])
    __half* Ps = Qs;

    int tid = threadIdx.x;
    int z = blockIdx.y;
    int b = z / HH, h = z % HH;
    int q0 = blockIdx.x * 128;
    int lane = tid & 31, wid = tid >> 5;
    int lr = lane >> 2, lc = lane & 3;

    const __half* Qg = qg + ((ll)(b * SS + q0)) * DD + h * DK;
#pragma unroll
    for (int it = 0; it < 4; it++) {
        int i = it * 256 + tid;
        int row = i >> 3, c8 = i & 7;
        cpa16(Qs + row * QSH + c8 * 8, Qg + (ll)row * DD + c8 * 8, 16);
    }
    asm volatile("cp.async.commit_group;\n");

    auto pf = [&](int i) {
        int st = i & 1;
        const __half* Kg = kg + ((ll)(b * SS + i * 64)) * DD + h * DK;
        const __half* Vg = vtg + ((ll)(b * DD + h * DK)) * SS + i * 64;
#pragma unroll
        for (int it = 0; it < 2; it++) {
            int j = it * 256 + tid;
            int row = j >> 3, c8 = j & 7;
            cpa16(Ks + st * 64 * QSH + row * QSH + c8 * 8, Kg + (ll)row * DD + c8 * 8, 16);
        }
#pragma unroll
        for (int it = 0; it < 2; it++) {
            int j = it * 256 + tid;
            int row = j >> 3, c8 = j & 7;    // row = dk
            cpa16(Vs + st * 64 * QSH + row * QSH + c8 * 8, Vg + (ll)row * SS + c8 * 8, 16);
        }
    };
    pf(0);
    asm volatile("cp.async.commit_group;\n");

    // Q fragments register-resident: 4 ksteps of dk16
    asm volatile("cp.async.wait_group 1;\n");
    __syncthreads();
    uint32_t qf[4][4];
    int aoffQ = (wid * 16 + (lane & 15)) * QSH + (lane >> 4) * 8;
#pragma unroll
    for (int ks = 0; ks < 4; ks++) ldsm4(qf[ks], Qs + aoffQ + ks * 16);

    // B-side (no-trans) lane offsets for [n][k] tiles
    int brow = (lane & 7) + (lane >> 4) * 8;       // n within 16-group
    int bkof = ((lane >> 3) & 1) * 8;              // k offset

    float4 oacc[8];
#pragma unroll
    for (int nt = 0; nt < 8; nt++) oacc[nt] = make_float4(0.f, 0.f, 0.f, 0.f);
    float m0 = -1e30f, m1 = -1e30f, l0 = 0.f, l1 = 0.f;
    int r0 = wid * 16 + lr, r1 = r0 + 8;
    const uint2* mp0 = (const uint2*)(mb + ((ll)(b * SS + q0 + r0)) * 32);
    const uint2* mp1 = (const uint2*)(mb + ((ll)(b * SS + q0 + r1)) * 32);

    constexpr int NIT = SS / 64;
    for (int i = 0; i < NIT; i++) {
        asm volatile("cp.async.wait_group 0;\n");
        __syncthreads();
        if (i + 1 < NIT) {
            pf(i + 1);
            asm volatile("cp.async.commit_group;\n");
        }
        const __half* Kst = Ks + (i & 1) * 64 * QSH;
        const __half* Vst = Vs + (i & 1) * 64 * QSH;

        // S = Q @ K^T  (16 rows x 64 keys; K stored [key][dk])
        float4 s[8];
#pragma unroll
        for (int nt = 0; nt < 8; nt++) s[nt] = make_float4(0.f, 0.f, 0.f, 0.f);
#pragma unroll
        for (int ks = 0; ks < 4; ks++) {
            uint32_t bf[8][2];
#pragma unroll
            for (int p = 0; p < 4; p++) {
                uint32_t t4[4];
                ldsm4(t4, Kst + (p * 16 + brow) * QSH + ks * 16 + bkof);
                bf[2 * p][0] = t4[0]; bf[2 * p][1] = t4[1];
                bf[2 * p + 1][0] = t4[2]; bf[2 * p + 1][1] = t4[3];
            }
#pragma unroll
            for (int nt = 0; nt < 8; nt++) mma16(s[nt], qf[ks], bf[nt]);
        }
        // scale + bitmask
        uint2 w0 = mp0[i];
        uint2 w1 = mp1[i];
#pragma unroll
        for (int nt = 0; nt < 8; nt++) {
            int bit = (nt & 3) * 8 + lc * 2;
            unsigned u0 = (nt < 4) ? w0.x : w0.y;
            unsigned u1 = (nt < 4) ? w1.x : w1.y;
            s[nt].x = ((u0 >> bit) & 1u)       ? s[nt].x * 0.125f : -1e9f;
            s[nt].y = ((u0 >> (bit + 1)) & 1u) ? s[nt].y * 0.125f : -1e9f;
            s[nt].z = ((u1 >> bit) & 1u)       ? s[nt].z * 0.125f : -1e9f;
            s[nt].w = ((u1 >> (bit + 1)) & 1u) ? s[nt].w * 0.125f : -1e9f;
        }
        // warp-local row max
        float mx0 = -1e30f, mx1 = -1e30f;
#pragma unroll
        for (int nt = 0; nt < 8; nt++) {
            mx0 = fmaxf(mx0, fmaxf(s[nt].x, s[nt].y));
            mx1 = fmaxf(mx1, fmaxf(s[nt].z, s[nt].w));
        }
#pragma unroll
        for (int o = 1; o <= 2; o <<= 1) {
            mx0 = fmaxf(mx0, __shfl_xor_sync(0xffffffff, mx0, o));
            mx1 = fmaxf(mx1, __shfl_xor_sync(0xffffffff, mx1, o));
        }
        float nm0 = fmaxf(m0, mx0), nm1 = fmaxf(m1, mx1);
        float sc0 = __expf(m0 - nm0), sc1 = __expf(m1 - nm1);
        m0 = nm0; m1 = nm1;
        // exp + store P fp16 + row sums
        float su0 = 0.f, su1 = 0.f;
#pragma unroll
        for (int nt = 0; nt < 8; nt++) {
            int col = nt * 8 + lc * 2;
            float e0 = __expf(s[nt].x - m0), e1 = __expf(s[nt].y - m0);
            float e2 = __expf(s[nt].z - m1), e3 = __expf(s[nt].w - m1);
            su0 += e0 + e1; su1 += e2 + e3;
            *(__half2*)(Ps + r0 * QSH + col) = __floats2half2_rn(e0, e1);
            *(__half2*)(Ps + r1 * QSH + col) = __floats2half2_rn(e2, e3);
        }
#pragma unroll
        for (int o = 1; o <= 2; o <<= 1) {
            su0 += __shfl_xor_sync(0xffffffff, su0, o);
            su1 += __shfl_xor_sync(0xffffffff, su1, o);
        }
        l0 = l0 * sc0 + su0;
        l1 = l1 * sc1 + su1;
#pragma unroll
        for (int nt = 0; nt < 8; nt++) {
            oacc[nt].x *= sc0; oacc[nt].y *= sc0;
            oacc[nt].z *= sc1; oacc[nt].w *= sc1;
        }
        __syncwarp();
        // O += P @ V  (P [m][key]; V [dk][key] -> no-trans B)
#pragma unroll
        for (int ks = 0; ks < 4; ks++) {
            uint32_t af[4];
            ldsm4(af, Ps + aoffQ + ks * 16);
            uint32_t bf[8][2];
#pragma unroll
            for (int p = 0; p < 4; p++) {
                uint32_t t4[4];
                ldsm4(t4, Vst + (p * 16 + brow) * QSH + ks * 16 + bkof);
                bf[2 * p][0] = t4[0]; bf[2 * p][1] = t4[1];
                bf[2 * p + 1][0] = t4[2]; bf[2 * p + 1][1] = t4[3];
            }
#pragma unroll
            for (int nt = 0; nt < 8; nt++) mma16(oacc[nt], af, bf[nt]);
        }
    }

    float inv0 = 1.f / l0, inv1 = 1.f / l1;
    __half* cg = ctx + ((ll)(b * SS + q0)) * DD + h * DK;
#pragma unroll
    for (int nt = 0; nt < 8; nt++) {
        int col = nt * 8 + lc * 2;
        *(__half2*)(cg + (ll)r0 * DD + col) = __floats2half2_rn(oacc[nt].x * inv0, oacc[nt].y * inv0);
        *(__half2*)(cg + (ll)r1 * DD + col) = __floats2half2_rn(oacc[nt].z * inv1, oacc[nt].w * inv1);
    }
}

// ---------------- gate + routing (fp32 x2b) ----------------
__global__ void zero_counts_k(int* counts) {
    if (threadIdx.x < EE) counts[threadIdx.x] = 0;
}
__global__ void gate_route_k(const float* __restrict__ x2, const float* __restrict__ gw,
                             const float* __restrict__ gb, int* counts, int* etok,
                             int* texp, int* tslot, float* tw) {
    int t = blockIdx.x;
    __shared__ float xs[DD];
    __shared__ float logits[EE];
    const float* row = x2 + (ll)t * DD;
    for (int i = threadIdx.x; i < DD; i += 256) xs[i] = row[i];
    __syncthreads();
    int w = threadIdx.x / 32, lane = threadIdx.x % 32;
    float s = 0.f;
    for (int d = lane; d < DD; d += 32) s += xs[d] * gw[d * EE + w];
    for (int o = 16; o; o >>= 1) s += __shfl_xor_sync(0xffffffff, s, o);
    if (lane == 0) logits[w] = s + gb[w];
    __syncthreads();
    if (threadIdx.x == 0) {
        float p[EE];
        float m = -1e30f;
        for (int e = 0; e < EE; e++) m = fmaxf(m, logits[e]);
        float sum = 0.f;
        for (int e = 0; e < EE; e++) { p[e] = __expf(logits[e] - m); sum += p[e]; }
        for (int e = 0; e < EE; e++) p[e] /= sum;
        int i0 = 0;
        for (int e = 1; e < EE; e++) if (p[e] > p[i0]) i0 = e;
        int i1 = -1;
        for (int e = 0; e < EE; e++) {
            if (e == i0) continue;
            if (i1 < 0 || p[e] > p[i1]) i1 = e;
        }
        float denom = p[i0] + p[i1] + 1e-6f;
        int s0 = atomicAdd(&counts[i0], 1);
        int s1 = atomicAdd(&counts[i1], 1);
        etok[i0 * TT + s0] = t;
        etok[i1 * TT + s1] = t;
        texp[t * 2] = i0; texp[t * 2 + 1] = i1;
        tslot[t * 2] = s0; tslot[t * 2 + 1] = s1;
        tw[t * 2] = p[i0] / denom; tw[t * 2 + 1] = p[i1] / denom;
    }
}

// ---------------- final combine ----------------
__global__ void combine_k(const float* __restrict__ xres, const int* __restrict__ texp,
                          const int* __restrict__ tslot, const float* __restrict__ tw,
                          const float* __restrict__ moe, float* __restrict__ out) {
    int t = blockIdx.x;
    int e0 = texp[t * 2], e1 = texp[t * 2 + 1];
    int s0 = tslot[t * 2], s1 = tslot[t * 2 + 1];
    float w0 = tw[t * 2], w1 = tw[t * 2 + 1];
    const float* m0 = moe + ((size_t)e0 * TT + s0) * DD;
    const float* m1 = moe + ((size_t)e1 * TT + s1) * DD;
    const float* xr = xres + (ll)t * DD;
    float* o = out + (ll)t * DD;
    for (int i = threadIdx.x; i < DD; i += 256)
        o[i] = xr[i] + w0 * m0[i] + w1 * m1[i];
}

// ---------------- host side ----------------
static void* devPtr(const void* sym) {
    void* p = nullptr;
    cudaGetSymbolAddress(&p, sym);
    return p;
}

extern "C" void kernel_launch(void* const* d_in, const int* in_sizes, int n_in,
                              void* d_out, int out_size) {
    const float* x    = (const float*)d_in[0];
    const int*   mask = (const int*)  d_in[1];
    const float* wq1 = (const float*)d_in[2];  const float* bq1 = (const float*)d_in[3];
    const float* wq2 = (const float*)d_in[4];  const float* bq2 = (const float*)d_in[5];
    const float* wk1 = (const float*)d_in[6];  const float* bk1 = (const float*)d_in[7];
    const float* wk2 = (const float*)d_in[8];  const float* bk2 = (const float*)d_in[9];
    const float* wv1 = (const float*)d_in[10]; const float* bv1 = (const float*)d_in[11];
    const float* wv2 = (const float*)d_in[12]; const float* bv2 = (const float*)d_in[13];
    const float* wo  = (const float*)d_in[14]; const float* bo  = (const float*)d_in[15];
    const float* ln1g = (const float*)d_in[16]; const float* ln1b = (const float*)d_in[17];
    const float* ln2g = (const float*)d_in[18]; const float* ln2b = (const float*)d_in[19];
    const float* gw  = (const float*)d_in[20]; const float* gb  = (const float*)d_in[21];
    const float* ew1 = (const float*)d_in[22]; const float* eb1 = (const float*)d_in[23];
    const float* ew2 = (const float*)d_in[24]; const float* eb2 = (const float*)d_in[25];
    const float* ew3 = (const float*)d_in[26]; const float* eb3 = (const float*)d_in[27];
    float* out = (float*)d_out;

    __half* hw   = (__half*)devPtr(g_hw);
    __half* hx2a = (__half*)devPtr(g_hx2a);
    __half* hqk  = (__half*)devPtr(g_hqk);
    __half* hvt  = (__half*)devPtr(g_hvt);
    __half* hctx = (__half*)devPtr(g_hctx);
    __half* hx2b = (__half*)devPtr(g_hx2b);
    __half* hemid= (__half*)devPtr(g_hemid);
    float* x2b  = (float*)devPtr(g_x2b);
    float* xres = (float*)devPtr(g_xres);
    float* moe  = (float*)devPtr(g_moe);
    unsigned* mb = (unsigned*)devPtr(g_mb);
    int* counts = (int*)devPtr(g_counts);
    int* etok   = (int*)devPtr(g_etok);
    int* texp   = (int*)devPtr(g_texp);
    int* tslot  = (int*)devPtr(g_tslot);
    float* tw   = (float*)devPtr(g_tw);

    __half* hq = hqk;
    __half* hk = hqk + (ll)TT * DD;

    auto kDP = tcgd<0,1,0,1>;                 // dual proj (ZSEL, VT for z==2)
    auto kDM = tcgd<1,0,1,0>;                 // dual MoE up (gather, per-z)
    auto kO1 = tcg<128,256,2,8,1,0,0>;        // oproj + residual
    auto kM2 = tcg<128,256,2,8,0,0,1>;        // moe down (per-z)

    int smD  = (2 * (64 * 40 + 2 * 32 * 136)) * 2 + 256;
    int smP  = (3 * (128 * 40 + 32 * 264)) * 2 + 256;
    int smFL = (128 * QSH + 4 * 64 * QSH) * 2;
    cudaFuncSetAttribute(kDP, cudaFuncAttributeMaxDynamicSharedMemorySize, smD);
    cudaFuncSetAttribute(kDM, cudaFuncAttributeMaxDynamicSharedMemorySize, smD);
    cudaFuncSetAttribute(kO1, cudaFuncAttributeMaxDynamicSharedMemorySize, smP);
    cudaFuncSetAttribute(kM2, cudaFuncAttributeMaxDynamicSharedMemorySize, smP);
    cudaFuncSetAttribute(flash_k, cudaFuncAttributeMaxDynamicSharedMemorySize, smFL);

    // 0) weight conversion (fp32 -> fp16)
    cvt_k<<<WP/1024, 256>>>(wq1, hw + OFF_Q1, WP);
    cvt_k<<<WP/1024, 256>>>(wq2, hw + OFF_Q2, WP);
    cvt_k<<<WP/1024, 256>>>(wk1, hw + OFF_K1, WP);
    cvt_k<<<WP/1024, 256>>>(wk2, hw + OFF_K2, WP);
    cvt_k<<<WP/1024, 256>>>(wv1, hw + OFF_V1, WP);
    cvt_k<<<WP/1024, 256>>>(wv2, hw + OFF_V2, WP);
    cvt_k<<<WP/1024, 256>>>(wo,  hw + OFF_WO, WP);
    ll nE = (ll)EE * DD * FF;
    cvt_k<<<(int)(nE/1024), 256>>>(ew1, hw + OFF_E1, nE);
    cvt_k<<<(int)(nE/1024), 256>>>(ew3, hw + OFF_E3, nE);
    cvt_k<<<(int)(nE/1024), 256>>>(ew2, hw + OFF_E2, nE);

    // 1) LN1 (fp16) + mask bitpack
    ln_k<<<TT, 256>>>(x, ln1g, ln1b, hx2a, nullptr);
    packmask_k<<<TT / 8, 256>>>(mask, mb);

    // 2) fused SwiGLU projections; z=2 writes V transposed fp16
    kDP<<<dim3(TT/64, DD/128, 3), 256, smD>>>(hx2a, DD,
        hw + OFF_Q1, hw + OFF_K1, hw + OFF_V1,
        hw + OFF_Q2, hw + OFF_K2, hw + OFF_V2, DD, 0,
        bq1, bk1, bv1, bq2, bk2, bv2, 0,
        hqk, DD, (ll)TT * DD, hvt,
        TT, nullptr, DD, nullptr);

    // 3+4) flash attention (fp16)
    flash_k<<<dim3(SS / 128, BB * HH), 256, smFL>>>(hq, hk, hvt, mb, hctx);

    // 5) out proj + residual (fp32 out)
    kO1<<<dim3(TT/128, DD/256, 1), 512, smP>>>(hctx, DD, 0,
        hw + OFF_WO, DD, 0, bo, 0, x,
        xres, DD, 0,
        TT, nullptr, DD, nullptr);

    // 6) LN2 (fp16 + fp32 for gate)
    ln_k<<<TT, 256>>>(xres, ln2g, ln2b, hx2b, x2b);

    // 7) gate + routing
    zero_counts_k<<<1, 32>>>(counts);
    gate_route_k<<<TT, 256>>>(x2b, gw, gb, counts, etok, texp, tslot, tw);

    // 8) MoE: dual up-proj (fp16 out) + down-proj (fp32 out), z = expert
    kDM<<<dim3(TT/64, FF/128, EE), 256, smD>>>(hx2b, DD,
        hw + OFF_E1, nullptr, nullptr, hw + OFF_E3, nullptr, nullptr, FF, (ll)DD * FF,
        eb1, nullptr, nullptr, eb3, nullptr, nullptr, FF,
        hemid, FF, (ll)TT * FF, nullptr,
        0, counts, DD, etok);
    kM2<<<dim3(TT/128, DD/256, EE), 512, smP>>>(hemid, FF, (ll)TT * FF,
        hw + OFF_E2, DD, (ll)FF * DD, eb2, DD, nullptr,
        moe, DD, (ll)TT * DD,
        0, counts, FF, nullptr);

    // 9) combine
    combine_k<<<TT, 256>>>(xres, texp, tslot, tw, moe, out);
}

// round 15
// speedup vs baseline: 1.5088x; 1.0105x over previous
#include <cuda_runtime.h>
#include <cuda_fp16.h>
#include <math.h>
#include <stdint.h>

// Problem dims
#define BB 4
#define SS 1024
#define DD 1024
#define FF 2048
#define HH 16
#define EE 8
#define DK 64
#define TT (BB*SS)          // 4096 tokens
typedef long long ll;

// fp16 weight scratch offsets (halves)
#define WP (DD*DD)
#define NE ((ll)EE*DD*FF)
#define OFF_Q1 0
#define OFF_Q2 (1*WP)
#define OFF_K1 (2*WP)
#define OFF_K2 (3*WP)
#define OFF_V1 (4*WP)
#define OFF_V2 (5*WP)
#define OFF_WO (6*WP)
#define OFF_E1 ((ll)7*WP)
#define OFF_E3 (OFF_E1 + NE)
#define OFF_E2 (OFF_E3 + NE)
#define HW_TOTAL (OFF_E2 + (ll)EE*FF*DD)

// ---------------- static device scratch ----------------
__device__ __half g_hw[HW_TOTAL];               // fp16 weights (~115MB)
__device__ __half g_hx2a[TT*DD];
__device__ __half g_hqk[2*TT*DD];               // q,k fp16
__device__ __half g_hvt[TT*DD];                 // V transposed fp16: [b*DD+hd][s]
__device__ __half g_hctx[TT*DD];
__device__ __half g_hx2b[TT*DD];
__device__ __half g_hemid[(size_t)EE*TT*FF];    // MoE mid fp16
__device__ float g_x2b[TT*DD];                  // fp32 copy for gate
__device__ float g_xres[TT*DD];
__device__ unsigned g_mb[(size_t)TT*32];
__device__ int   g_counts[EE];
__device__ int   g_etok[EE*TT];
__device__ float g_wslot[EE*TT];

// ---------------- helpers ----------------
__device__ __forceinline__ float blockReduceSum(float v, float* sh) {
    int tid = threadIdx.x;
    sh[tid] = v; __syncthreads();
    for (int s = 128; s > 0; s >>= 1) {
        if (tid < s) sh[tid] += sh[tid + s];
        __syncthreads();
    }
    float r = sh[0]; __syncthreads();
    return r;
}
__device__ __forceinline__ void mma16(float4& d, const uint32_t* a, const uint32_t* b) {
    asm volatile(
        "mma.sync.aligned.m16n8k16.row.col.f32.f16.f16.f32 "
        "{%0,%1,%2,%3}, {%4,%5,%6,%7}, {%8,%9}, {%0,%1,%2,%3};"
        : "+f"(d.x), "+f"(d.y), "+f"(d.z), "+f"(d.w)
        : "r"(a[0]), "r"(a[1]), "r"(a[2]), "r"(a[3]), "r"(b[0]), "r"(b[1]));
}
__device__ __forceinline__ void cpa16(void* dst, const void* src, int sz) {
    uint32_t d = (uint32_t)__cvta_generic_to_shared(dst);
    asm volatile("cp.async.cg.shared.global [%0], [%1], 16, %2;\n"
                 :: "r"(d), "l"(src), "r"(sz));
}
__device__ __forceinline__ void ldsm4(uint32_t* d, const __half* p) {
    uint32_t a = (uint32_t)__cvta_generic_to_shared(p);
    asm volatile("ldmatrix.sync.aligned.m8n8.x4.shared.b16 {%0,%1,%2,%3}, [%4];"
                 : "=r"(d[0]), "=r"(d[1]), "=r"(d[2]), "=r"(d[3]) : "r"(a));
}
__device__ __forceinline__ void ldsm4t(uint32_t* d, const __half* p) {
    uint32_t a = (uint32_t)__cvta_generic_to_shared(p);
    asm volatile("ldmatrix.sync.aligned.m8n8.x4.trans.shared.b16 {%0,%1,%2,%3}, [%4];"
                 : "=r"(d[0]), "=r"(d[1]), "=r"(d[2]), "=r"(d[3]) : "r"(a));
}
__device__ __forceinline__ float siluf(float x) {
    return x / (1.f + __expf(-x));
}

// ---------------- batched fp32 -> fp16 convert ----------------
struct Ptr7 { const float* p[7]; };
__global__ void cvt7_k(Ptr7 ps, __half* __restrict__ dst) {
    int z = blockIdx.y;
    ll i = ((ll)blockIdx.x * 256 + threadIdx.x) * 8;
    if (i >= WP) return;
    const float* s = ps.p[z] + i;
    __half2* d = (__half2*)(dst + (ll)z * WP + i);
    float4 v0 = *(const float4*)s;
    float4 v1 = *(const float4*)(s + 4);
    d[0] = __floats2half2_rn(v0.x, v0.y);
    d[1] = __floats2half2_rn(v0.z, v0.w);
    d[2] = __floats2half2_rn(v1.x, v1.y);
    d[3] = __floats2half2_rn(v1.z, v1.w);
}
struct Ptr3 { const float* p[3]; };
__global__ void cvt3_k(Ptr3 ps, __half* __restrict__ dst) {
    int z = blockIdx.y;
    ll i = ((ll)blockIdx.x * 256 + threadIdx.x) * 8;
    if (i >= NE) return;
    const float* s = ps.p[z] + i;
    __half2* d = (__half2*)(dst + (ll)z * NE + i);
    float4 v0 = *(const float4*)s;
    float4 v1 = *(const float4*)(s + 4);
    d[0] = __floats2half2_rn(v0.x, v0.y);
    d[1] = __floats2half2_rn(v0.z, v0.w);
    d[2] = __floats2half2_rn(v1.x, v1.y);
    d[3] = __floats2half2_rn(v1.z, v1.w);
}

// ---------------- LayerNorm (fp16 out, optional fp32 out) ----------------
__global__ void ln_k(const float* __restrict__ x, const float* __restrict__ g,
                     const float* __restrict__ b, __half* __restrict__ out16,
                     float* __restrict__ out32) {
    __shared__ float sh[256];
    int r = blockIdx.x;
    const float* row = x + (size_t)r * DD;
    float s = 0.f;
    for (int i = threadIdx.x; i < DD; i += 256) s += row[i];
    float mean = blockReduceSum(s, sh) * (1.0f / DD);
    float v = 0.f;
    for (int i = threadIdx.x; i < DD; i += 256) {
        float d = row[i] - mean; v += d * d;
    }
    float var = blockReduceSum(v, sh) * (1.0f / DD);
    float inv = rsqrtf(var + 1e-5f);
    for (int i = threadIdx.x; i < DD; i += 256) {
        float val = (row[i] - mean) * inv * g[i] + b[i];
        out16[(size_t)r * DD + i] = __float2half(val);
        if (out32) out32[(size_t)r * DD + i] = val;
    }
}

// ---------------- mask bitpack ----------------
__global__ void packmask_k(const int* __restrict__ mask, unsigned* __restrict__ mb) {
    int wid = threadIdx.x >> 5, lane = threadIdx.x & 31;
    ll row = (ll)blockIdx.x * 8 + wid;
    const int* mrow = mask + row * SS;
#pragma unroll
    for (int w = 0; w < 32; w++) {
        unsigned word = __ballot_sync(0xffffffff, mrow[w * 32 + lane] != 0);
        if (lane == 0) mb[row * 32 + w] = word;
    }
}

// ================= fp16 tensor-core GEMM (single, 3-stage) =================
// EPI: 0 = +bias; 1 = +bias + S residual -> C and Caux;
//      2 = atomicAdd(C[tok[r]] , wsl[r]*(acc+bias))  [fused MoE combine]
template<int BM, int BN, int WGM, int WGN, int EPI, int GATHER, int MPZ>
__global__ void __launch_bounds__(WGM*WGN*32)
tcg(const __half* __restrict__ A, int lda, ll sAz,
    const __half* __restrict__ B0, int ldb, ll sBz,
    const float* __restrict__ bias0, ll sBiasZ,
    const float* __restrict__ S, float* __restrict__ Caux,
    const float* __restrict__ wsl0,
    float* __restrict__ C, int ldc, ll sCz,
    int M, const int* __restrict__ Mptr, int Kd,
    const int* __restrict__ tok) {
    constexpr int NTH = WGM * WGN * 32;
    constexpr int BK = 32;
    constexpr int ASTR = BK + 8;
    constexpr int BSTR = BN + 8;
    constexpr int ASZ = BM * ASTR;
    constexpr int BSZ = BK * BSTR;
    constexpr int STG = ASZ + BSZ;
    constexpr int WM = BM / WGM;
    constexpr int WN = BN / WGN;
    constexpr int MT = WM / 16;
    constexpr int NT = WN / 8;

    int zb = blockIdx.z;
    if (MPZ) M = Mptr[zb];
    else if (Mptr) M = *Mptr;
    int bm0 = blockIdx.x * BM;
    if (bm0 >= M) return;
    int bn0 = blockIdx.y * BN;

    const __half* Bm = B0 + (ll)zb * sBz;
    const float* bias = bias0 ? bias0 + (ll)zb * sBiasZ : nullptr;
    A += (ll)zb * sAz;
    C += (ll)zb * sCz;
    const float* wsl = wsl0;
    if (MPZ && tok) tok += (ll)zb * TT;
    if (MPZ && wsl) wsl += (ll)zb * TT;

    extern __shared__ __half smh[];
    int* toks = (int*)(smh + 3 * STG);
    int tid = threadIdx.x;

    if (GATHER) {
        for (int i = tid; i < BM; i += NTH) {
            int gr = bm0 + i;
            toks[i] = (gr < M) ? tok[gr] : -1;
        }
        __syncthreads();
    }

    int wid = tid >> 5, lane = tid & 31;
    int wm = wid / WGN, wn = wid - wm * WGN;
    int lr = lane >> 2, lc = lane & 3;

    int aoffA[MT];
#pragma unroll
    for (int mt = 0; mt < MT; mt++)
        aoffA[mt] = (wm * WM + mt * 16 + (lane & 15)) * ASTR + (lane >> 4) * 8;
    int krow = (lane & 7) + ((lane >> 3) & 1) * 8;
    int ncol = (lane >> 4) * 8;

    auto fill = [&](int st, int k0) {
        __half* As = smh + st * STG;
        __half* Bs = As + ASZ;
#pragma unroll
        for (int it = 0; it < BM * 4 / NTH; it++) {
            int i = it * NTH + tid;
            int row = i >> 2, c8 = i & 3;
            __half* dst = As + row * ASTR + c8 * 8;
            const __half* src;
            int sz = 16;
            if (GATHER) {
                int tk = toks[row];
                src = A + (ll)(tk < 0 ? 0 : tk) * lda + k0 + c8 * 8;
                if (tk < 0) sz = 0;
            } else {
                src = A + (ll)(bm0 + row) * lda + k0 + c8 * 8;
            }
            cpa16(dst, src, sz);
        }
        constexpr int RC = BN / 8;
#pragma unroll
        for (int it = 0; it < BK * RC / NTH; it++) {
            int i = it * NTH + tid;
            int kk = i / RC, c8 = i - kk * RC;
            cpa16(Bs + kk * BSTR + c8 * 8,
                  Bm + (ll)(k0 + kk) * ldb + bn0 + c8 * 8, 16);
        }
    };

    float4 acc[MT][NT];
#pragma unroll
    for (int i = 0; i < MT; i++)
#pragma unroll
        for (int j = 0; j < NT; j++) acc[i][j] = make_float4(0.f, 0.f, 0.f, 0.f);

    int nIt = Kd / BK;
    fill(0, 0);
    asm volatile("cp.async.commit_group;\n");
    if (nIt > 1) {
        fill(1, BK);
        asm volatile("cp.async.commit_group;\n");
    }

    for (int itK = 0; itK < nIt; itK++) {
        if (itK + 1 < nIt) asm volatile("cp.async.wait_group 1;\n");
        else               asm volatile("cp.async.wait_group 0;\n");
        __syncthreads();
        const __half* As = smh + (itK % 3) * STG;
        const __half* Bs = As + ASZ;
#pragma unroll
        for (int ks = 0; ks < 2; ks++) {
            uint32_t af[MT][4];
#pragma unroll
            for (int mt = 0; mt < MT; mt++)
                ldsm4(af[mt], As + aoffA[mt] + ks * 16);
            uint32_t bf[NT][2];
#pragma unroll
            for (int np = 0; np < NT / 2; np++) {
                uint32_t t4[4];
                ldsm4t(t4, Bs + (ks * 16 + krow) * BSTR + wn * WN + np * 16 + ncol);
                bf[2 * np][0] = t4[0]; bf[2 * np][1] = t4[1];
                bf[2 * np + 1][0] = t4[2]; bf[2 * np + 1][1] = t4[3];
            }
#pragma unroll
            for (int mt = 0; mt < MT; mt++)
#pragma unroll
                for (int nt = 0; nt < NT; nt++)
                    mma16(acc[mt][nt], af[mt], bf[nt]);
        }
        if (itK + 2 < nIt) {
            fill((itK + 2) % 3, (itK + 2) * BK);
            asm volatile("cp.async.commit_group;\n");
        }
    }

#pragma unroll
    for (int mt = 0; mt < MT; mt++) {
        int r0 = bm0 + wm * WM + mt * 16 + lr;
        int r1 = r0 + 8;
        int t0 = 0, t1 = 0;
        float ws0 = 0.f, ws1 = 0.f;
        if (EPI == 2) {
            if (r0 < M) { t0 = tok[r0]; ws0 = wsl[r0]; }
            if (r1 < M) { t1 = tok[r1]; ws1 = wsl[r1]; }
        }
#pragma unroll
        for (int nt = 0; nt < NT; nt++) {
            int col = bn0 + wn * WN + nt * 8 + lc * 2;
            float v0 = acc[mt][nt].x, v1 = acc[mt][nt].y;
            float v2 = acc[mt][nt].z, v3 = acc[mt][nt].w;
            if (bias) {
                float b0 = bias[col], b1 = bias[col + 1];
                v0 += b0; v1 += b1; v2 += b0; v3 += b1;
            }
            if (EPI == 2) {
                if (r0 < M) {
                    atomicAdd(&C[(ll)t0 * ldc + col],     ws0 * v0);
                    atomicAdd(&C[(ll)t0 * ldc + col + 1], ws0 * v1);
                }
                if (r1 < M) {
                    atomicAdd(&C[(ll)t1 * ldc + col],     ws1 * v2);
                    atomicAdd(&C[(ll)t1 * ldc + col + 1], ws1 * v3);
                }
            } else {
                if (EPI == 1) {
                    if (r0 < M) {
                        v0 += S[(ll)r0 * ldc + col];
                        v1 += S[(ll)r0 * ldc + col + 1];
                    }
                    if (r1 < M) {
                        v2 += S[(ll)r1 * ldc + col];
                        v3 += S[(ll)r1 * ldc + col + 1];
                    }
                }
                if (r0 < M) {
                    C[(ll)r0 * ldc + col] = v0;
                    C[(ll)r0 * ldc + col + 1] = v1;
                    if (EPI == 1) {
                        Caux[(ll)r0 * ldc + col] = v0;
                        Caux[(ll)r0 * ldc + col + 1] = v1;
                    }
                }
                if (r1 < M) {
                    C[(ll)r1 * ldc + col] = v2;
                    C[(ll)r1 * ldc + col + 1] = v3;
                    if (EPI == 1) {
                        Caux[(ll)r1 * ldc + col] = v2;
                        Caux[(ll)r1 * ldc + col + 1] = v3;
                    }
                }
            }
        }
    }
}

// ================= fp16 dual GEMM: out = silu(A@Wa+ba)*(A@Wb+bb), fp16 out =================
template<int GATHER, int ZSEL, int MPZ, int VT>
__global__ void __launch_bounds__(256, 2)
tcgd(const __half* __restrict__ A, int lda,
     const __half* __restrict__ Ba0, const __half* __restrict__ Ba1, const __half* __restrict__ Ba2,
     const __half* __restrict__ Bb0, const __half* __restrict__ Bb1, const __half* __restrict__ Bb2,
     int ldb, ll sBz,
     const float* __restrict__ ba0, const float* __restrict__ ba1, const float* __restrict__ ba2,
     const float* __restrict__ bb0, const float* __restrict__ bb1, const float* __restrict__ bb2,
     ll sBiasZ,
     __half* __restrict__ C, int ldc, ll sCz,
     __half* __restrict__ vtout,
     int M, const int* __restrict__ Mptr, int Kd,
     const int* __restrict__ tok) {
    constexpr int NTH = 256;
    constexpr int BM = 64, BN = 128, BK = 32;
    constexpr int ASTR = 40, BSTR = BN + 8;
    constexpr int ASZ = BM * ASTR, BSZ = BK * BSTR;
    constexpr int STG = ASZ + 2 * BSZ;
    constexpr int MT = 2, NT = 4;

    int zb = blockIdx.z;
    if (MPZ) M = Mptr[zb];
    int bm0 = blockIdx.x * BM;
    if (bm0 >= M) return;
    int bn0 = blockIdx.y * BN;

    const __half* BA = ZSEL ? (zb == 0 ? Ba0 : (zb == 1 ? Ba1 : Ba2)) : Ba0 + (ll)zb * sBz;
    const __half* BBp = ZSEL ? (zb == 0 ? Bb0 : (zb == 1 ? Bb1 : Bb2)) : Bb0 + (ll)zb * sBz;
    const float* biasA = ZSEL ? (zb == 0 ? ba0 : (zb == 1 ? ba1 : ba2)) : ba0 + (ll)zb * sBiasZ;
    const float* biasB = ZSEL ? (zb == 0 ? bb0 : (zb == 1 ? bb1 : bb2)) : bb0 + (ll)zb * sBiasZ;
    C += (ll)zb * sCz;
    if (GATHER && MPZ) tok += (ll)zb * TT;

    extern __shared__ __half smh[];
    int* toks = (int*)(smh + 2 * STG);
    int tid = threadIdx.x;

    if (GATHER) {
        for (int i = tid; i < BM; i += NTH) {
            int gr = bm0 + i;
            toks[i] = (gr < M) ? tok[gr] : -1;
        }
        __syncthreads();
    }

    int wid = tid >> 5, lane = tid & 31;
    int wm = wid >> 2, wn = wid & 3;
    int lr = lane >> 2, lc = lane & 3;

    int aoffA[MT];
#pragma unroll
    for (int mt = 0; mt < MT; mt++)
        aoffA[mt] = (wm * 32 + mt * 16 + (lane & 15)) * ASTR + (lane >> 4) * 8;
    int krow = (lane & 7) + ((lane >> 3) & 1) * 8;
    int ncol = (lane >> 4) * 8;

    auto fill = [&](int st, int k0) {
        __half* As = smh + st * STG;
        __half* Bsa = As + ASZ;
        __half* Bsb = Bsa + BSZ;
#pragma unroll
        for (int it = 0; it < BM * 4 / NTH; it++) {
            int i = it * NTH + tid;
            int row = i >> 2, c8 = i & 3;
            __half* dst = As + row * ASTR + c8 * 8;
            const __half* src;
            int sz = 16;
            if (GATHER) {
                int tk = toks[row];
                src = A + (ll)(tk < 0 ? 0 : tk) * lda + k0 + c8 * 8;
                if (tk < 0) sz = 0;
            } else {
                src = A + (ll)(bm0 + row) * lda + k0 + c8 * 8;
            }
            cpa16(dst, src, sz);
        }
        constexpr int RC = BN / 8;  // 16
#pragma unroll
        for (int it = 0; it < BK * RC / NTH; it++) {
            int i = it * NTH + tid;
            int kk = i >> 4, c8 = i & 15;
            cpa16(Bsa + kk * BSTR + c8 * 8, BA  + (ll)(k0 + kk) * ldb + bn0 + c8 * 8, 16);
            cpa16(Bsb + kk * BSTR + c8 * 8, BBp + (ll)(k0 + kk) * ldb + bn0 + c8 * 8, 16);
        }
    };

    float4 accA[MT][NT], accB[MT][NT];
#pragma unroll
    for (int i = 0; i < MT; i++)
#pragma unroll
        for (int j = 0; j < NT; j++) {
            accA[i][j] = make_float4(0.f, 0.f, 0.f, 0.f);
            accB[i][j] = make_float4(0.f, 0.f, 0.f, 0.f);
        }

    int nIt = Kd / BK;
    fill(0, 0);
    asm volatile("cp.async.commit_group;\n");

    for (int itK = 0; itK < nIt; itK++) {
        asm volatile("cp.async.wait_group 0;\n");
        __syncthreads();
        if (itK + 1 < nIt) {
            fill((itK + 1) & 1, (itK + 1) * BK);
            asm volatile("cp.async.commit_group;\n");
        }
        const __half* As = smh + (itK & 1) * STG;
        const __half* Bsa = As + ASZ;
        const __half* Bsb = Bsa + BSZ;
#pragma unroll
        for (int ks = 0; ks < 2; ks++) {
            uint32_t af[MT][4];
#pragma unroll
            for (int mt = 0; mt < MT; mt++)
                ldsm4(af[mt], As + aoffA[mt] + ks * 16);
            uint32_t bfa[NT][2], bfb[NT][2];
#pragma unroll
            for (int np = 0; np < 2; np++) {
                uint32_t t4[4];
                ldsm4t(t4, Bsa + (ks * 16 + krow) * BSTR + wn * 32 + np * 16 + ncol);
                bfa[2 * np][0] = t4[0]; bfa[2 * np][1] = t4[1];
                bfa[2 * np + 1][0] = t4[2]; bfa[2 * np + 1][1] = t4[3];
                ldsm4t(t4, Bsb + (ks * 16 + krow) * BSTR + wn * 32 + np * 16 + ncol);
                bfb[2 * np][0] = t4[0]; bfb[2 * np][1] = t4[1];
                bfb[2 * np + 1][0] = t4[2]; bfb[2 * np + 1][1] = t4[3];
            }
#pragma unroll
            for (int mt = 0; mt < MT; mt++)
#pragma unroll
                for (int nt = 0; nt < NT; nt++) {
                    mma16(accA[mt][nt], af[mt], bfa[nt]);
                    mma16(accB[mt][nt], af[mt], bfb[nt]);
                }
        }
    }

#pragma unroll
    for (int mt = 0; mt < MT; mt++) {
        int r0 = bm0 + wm * 32 + mt * 16 + lr;
        int r1 = r0 + 8;
#pragma unroll
        for (int nt = 0; nt < NT; nt++) {
            int col = bn0 + wn * 32 + nt * 8 + lc * 2;
            float ba_ = biasA[col], ba1_ = biasA[col + 1];
            float bb_ = biasB[col], bb1_ = biasB[col + 1];
            float o0 = siluf(accA[mt][nt].x + ba_)  * (accB[mt][nt].x + bb_);
            float o1 = siluf(accA[mt][nt].y + ba1_) * (accB[mt][nt].y + bb1_);
            float o2 = siluf(accA[mt][nt].z + ba_)  * (accB[mt][nt].z + bb_);
            float o3 = siluf(accA[mt][nt].w + ba1_) * (accB[mt][nt].w + bb1_);
            if (VT && zb == 2) {
                int b0 = r0 >> 10, s0 = r0 & 1023;
                int b1 = r1 >> 10, s1 = r1 & 1023;
                vtout[((ll)(b0 * DD + col))     * SS + s0] = __float2half(o0);
                vtout[((ll)(b0 * DD + col + 1)) * SS + s0] = __float2half(o1);
                vtout[((ll)(b1 * DD + col))     * SS + s1] = __float2half(o2);
                vtout[((ll)(b1 * DD + col + 1)) * SS + s1] = __float2half(o3);
            } else {
                if (r0 < M)
                    *(__half2*)(C + (ll)r0 * ldc + col) = __floats2half2_rn(o0, o1);
                if (r1 < M)
                    *(__half2*)(C + (ll)r1 * ldc + col) = __floats2half2_rn(o2, o3);
            }
        }
    }
}

// ================= flash attention (fp16, warp-local softmax) =================
#define QSH 72
__global__ void __launch_bounds__(256, 2)
flash_k(const __half* __restrict__ qg, const __half* __restrict__ kg,
        const __half* __restrict__ vtg, const unsigned* __restrict__ mb,
        __half* __restrict__ ctx) {
    extern __shared__ __half smh[];
    __half* Qs = smh;
    __half* Ks = smh + 128 * QSH;
    __half* Vs = Ks + 2 * 64 * QSH;
    __half* Ps = Qs;

    int tid = threadIdx.x;
    int z = blockIdx.y;
    int b = z / HH, h = z % HH;
    int q0 = blockIdx.x * 128;
    int lane = tid & 31, wid = tid >> 5;
    int lr = lane >> 2, lc = lane & 3;

    const __half* Qg = qg + ((ll)(b * SS + q0)) * DD + h * DK;
#pragma unroll
    for (int it = 0; it < 4; it++) {
        int i = it * 256 + tid;
        int row = i >> 3, c8 = i & 7;
        cpa16(Qs + row * QSH + c8 * 8, Qg + (ll)row * DD + c8 * 8, 16);
    }
    asm volatile("cp.async.commit_group;\n");

    auto pf = [&](int i) {
        int st = i & 1;
        const __half* Kg = kg + ((ll)(b * SS + i * 64)) * DD + h * DK;
        const __half* Vg = vtg + ((ll)(b * DD + h * DK)) * SS + i * 64;
#pragma unroll
        for (int it = 0; it < 2; it++) {
            int j = it * 256 + tid;
            int row = j >> 3, c8 = j & 7;
            cpa16(Ks + st * 64 * QSH + row * QSH + c8 * 8, Kg + (ll)row * DD + c8 * 8, 16);
        }
#pragma unroll
        for (int it = 0; it < 2; it++) {
            int j = it * 256 + tid;
            int row = j >> 3, c8 = j & 7;
            cpa16(Vs + st * 64 * QSH + row * QSH + c8 * 8, Vg + (ll)row * SS + c8 * 8, 16);
        }
    };
    pf(0);
    asm volatile("cp.async.commit_group;\n");

    asm volatile("cp.async.wait_group 1;\n");
    __syncthreads();
    uint32_t qf[4][4];
    int aoffQ = (wid * 16 + (lane & 15)) * QSH + (lane >> 4) * 8;
#pragma unroll
    for (int ks = 0; ks < 4; ks++) ldsm4(qf[ks], Qs + aoffQ + ks * 16);

    int brow = (lane & 7) + (lane >> 4) * 8;
    int bkof = ((lane >> 3) & 1) * 8;

    float4 oacc[8];
#pragma unroll
    for (int nt = 0; nt < 8; nt++) oacc[nt] = make_float4(0.f, 0.f, 0.f, 0.f);
    float m0 = -1e30f, m1 = -1e30f, l0 = 0.f, l1 = 0.f;
    int r0 = wid * 16 + lr, r1 = r0 + 8;
    const uint2* mp0 = (const uint2*)(mb + ((ll)(b * SS + q0 + r0)) * 32);
    const uint2* mp1 = (const uint2*)(mb + ((ll)(b * SS + q0 + r1)) * 32);

    constexpr int NIT = SS / 64;
    for (int i = 0; i < NIT; i++) {
        asm volatile("cp.async.wait_group 0;\n");
        __syncthreads();
        if (i + 1 < NIT) {
            pf(i + 1);
            asm volatile("cp.async.commit_group;\n");
        }
        const __half* Kst = Ks + (i & 1) * 64 * QSH;
        const __half* Vst = Vs + (i & 1) * 64 * QSH;

        float4 s[8];
#pragma unroll
        for (int nt = 0; nt < 8; nt++) s[nt] = make_float4(0.f, 0.f, 0.f, 0.f);
#pragma unroll
        for (int ks = 0; ks < 4; ks++) {
            uint32_t bf[8][2];
#pragma unroll
            for (int p = 0; p < 4; p++) {
                uint32_t t4[4];
                ldsm4(t4, Kst + (p * 16 + brow) * QSH + ks * 16 + bkof);
                bf[2 * p][0] = t4[0]; bf[2 * p][1] = t4[1];
                bf[2 * p + 1][0] = t4[2]; bf[2 * p + 1][1] = t4[3];
            }
#pragma unroll
            for (int nt = 0; nt < 8; nt++) mma16(s[nt], qf[ks], bf[nt]);
        }
        uint2 w0 = mp0[i];
        uint2 w1 = mp1[i];
#pragma unroll
        for (int nt = 0; nt < 8; nt++) {
            int bit = (nt & 3) * 8 + lc * 2;
            unsigned u0 = (nt < 4) ? w0.x : w0.y;
            unsigned u1 = (nt < 4) ? w1.x : w1.y;
            s[nt].x = ((u0 >> bit) & 1u)       ? s[nt].x * 0.125f : -1e9f;
            s[nt].y = ((u0 >> (bit + 1)) & 1u) ? s[nt].y * 0.125f : -1e9f;
            s[nt].z = ((u1 >> bit) & 1u)       ? s[nt].z * 0.125f : -1e9f;
            s[nt].w = ((u1 >> (bit + 1)) & 1u) ? s[nt].w * 0.125f : -1e9f;
        }
        float mx0 = -1e30f, mx1 = -1e30f;
#pragma unroll
        for (int nt = 0; nt < 8; nt++) {
            mx0 = fmaxf(mx0, fmaxf(s[nt].x, s[nt].y));
            mx1 = fmaxf(mx1, fmaxf(s[nt].z, s[nt].w));
        }
#pragma unroll
        for (int o = 1; o <= 2; o <<= 1) {
            mx0 = fmaxf(mx0, __shfl_xor_sync(0xffffffff, mx0, o));
            mx1 = fmaxf(mx1, __shfl_xor_sync(0xffffffff, mx1, o));
        }
        float nm0 = fmaxf(m0, mx0), nm1 = fmaxf(m1, mx1);
        float sc0 = __expf(m0 - nm0), sc1 = __expf(m1 - nm1);
        m0 = nm0; m1 = nm1;
        float su0 = 0.f, su1 = 0.f;
#pragma unroll
        for (int nt = 0; nt < 8; nt++) {
            int col = nt * 8 + lc * 2;
            float e0 = __expf(s[nt].x - m0), e1 = __expf(s[nt].y - m0);
            float e2 = __expf(s[nt].z - m1), e3 = __expf(s[nt].w - m1);
            su0 += e0 + e1; su1 += e2 + e3;
            *(__half2*)(Ps + r0 * QSH + col) = __floats2half2_rn(e0, e1);
            *(__half2*)(Ps + r1 * QSH + col) = __floats2half2_rn(e2, e3);
        }
#pragma unroll
        for (int o = 1; o <= 2; o <<= 1) {
            su0 += __shfl_xor_sync(0xffffffff, su0, o);
            su1 += __shfl_xor_sync(0xffffffff, su1, o);
        }
        l0 = l0 * sc0 + su0;
        l1 = l1 * sc1 + su1;
#pragma unroll
        for (int nt = 0; nt < 8; nt++) {
            oacc[nt].x *= sc0; oacc[nt].y *= sc0;
            oacc[nt].z *= sc1; oacc[nt].w *= sc1;
        }
        __syncwarp();
#pragma unroll
        for (int ks = 0; ks < 4; ks++) {
            uint32_t af[4];
            ldsm4(af, Ps + aoffQ + ks * 16);
            uint32_t bf[8][2];
#pragma unroll
            for (int p = 0; p < 4; p++) {
                uint32_t t4[4];
                ldsm4(t4, Vst + (p * 16 + brow) * QSH + ks * 16 + bkof);
                bf[2 * p][0] = t4[0]; bf[2 * p][1] = t4[1];
                bf[2 * p + 1][0] = t4[2]; bf[2 * p + 1][1] = t4[3];
            }
#pragma unroll
            for (int nt = 0; nt < 8; nt++) mma16(oacc[nt], af, bf[nt]);
        }
    }

    float inv0 = 1.f / l0, inv1 = 1.f / l1;
    __half* cg = ctx + ((ll)(b * SS + q0)) * DD + h * DK;
#pragma unroll
    for (int nt = 0; nt < 8; nt++) {
        int col = nt * 8 + lc * 2;
        *(__half2*)(cg + (ll)r0 * DD + col) = __floats2half2_rn(oacc[nt].x * inv0, oacc[nt].y * inv0);
        *(__half2*)(cg + (ll)r1 * DD + col) = __floats2half2_rn(oacc[nt].z * inv1, oacc[nt].w * inv1);
    }
}

// ---------------- gate + routing ----------------
__global__ void zero_counts_k(int* counts) {
    if (threadIdx.x < EE) counts[threadIdx.x] = 0;
}
__global__ void gate_route_k(const float* __restrict__ x2, const float* __restrict__ gw,
                             const float* __restrict__ gb, int* counts, int* etok,
                             float* wslot) {
    int t = blockIdx.x;
    __shared__ float xs[DD];
    __shared__ float logits[EE];
    const float* row = x2 + (ll)t * DD;
    for (int i = threadIdx.x; i < DD; i += 256) xs[i] = row[i];
    __syncthreads();
    int w = threadIdx.x / 32, lane = threadIdx.x % 32;
    float s = 0.f;
    for (int d = lane; d < DD; d += 32) s += xs[d] * gw[d * EE + w];
    for (int o = 16; o; o >>= 1) s += __shfl_xor_sync(0xffffffff, s, o);
    if (lane == 0) logits[w] = s + gb[w];
    __syncthreads();
    if (threadIdx.x == 0) {
        float p[EE];
        float m = -1e30f;
        for (int e = 0; e < EE; e++) m = fmaxf(m, logits[e]);
        float sum = 0.f;
        for (int e = 0; e < EE; e++) { p[e] = __expf(logits[e] - m); sum += p[e]; }
        for (int e = 0; e < EE; e++) p[e] /= sum;
        int i0 = 0;
        for (int e = 1; e < EE; e++) if (p[e] > p[i0]) i0 = e;
        int i1 = -1;
        for (int e = 0; e < EE; e++) {
            if (e == i0) continue;
            if (i1 < 0 || p[e] > p[i1]) i1 = e;
        }
        float denom = p[i0] + p[i1] + 1e-6f;
        int s0 = atomicAdd(&counts[i0], 1);
        int s1 = atomicAdd(&counts[i1], 1);
        etok[i0 * TT + s0] = t;
        etok[i1 * TT + s1] = t;
        wslot[i0 * TT + s0] = p[i0] / denom;
        wslot[i1 * TT + s1] = p[i1] / denom;
    }
}

// ---------------- host side ----------------
static void* devPtr(const void* sym) {
    void* p = nullptr;
    cudaGetSymbolAddress(&p, sym);
    return p;
}

extern "C" void kernel_launch(void* const* d_in, const int* in_sizes, int n_in,
                              void* d_out, int out_size) {
    const float* x    = (const float*)d_in[0];
    const int*   mask = (const int*)  d_in[1];
    const float* wq1 = (const float*)d_in[2];  const float* bq1 = (const float*)d_in[3];
    const float* wq2 = (const float*)d_in[4];  const float* bq2 = (const float*)d_in[5];
    const float* wk1 = (const float*)d_in[6];  const float* bk1 = (const float*)d_in[7];
    const float* wk2 = (const float*)d_in[8];  const float* bk2 = (const float*)d_in[9];
    const float* wv1 = (const float*)d_in[10]; const float* bv1 = (const float*)d_in[11];
    const float* wv2 = (const float*)d_in[12]; const float* bv2 = (const float*)d_in[13];
    const float* wo  = (const float*)d_in[14]; const float* bo  = (const float*)d_in[15];
    const float* ln1g = (const float*)d_in[16]; const float* ln1b = (const float*)d_in[17];
    const float* ln2g = (const float*)d_in[18]; const float* ln2b = (const float*)d_in[19];
    const float* gw  = (const float*)d_in[20]; const float* gb  = (const float*)d_in[21];
    const float* ew1 = (const float*)d_in[22]; const float* eb1 = (const float*)d_in[23];
    const float* ew2 = (const float*)d_in[24]; const float* eb2 = (const float*)d_in[25];
    const float* ew3 = (const float*)d_in[26]; const float* eb3 = (const float*)d_in[27];
    float* out = (float*)d_out;

    __half* hw   = (__half*)devPtr(g_hw);
    __half* hx2a = (__half*)devPtr(g_hx2a);
    __half* hqk  = (__half*)devPtr(g_hqk);
    __half* hvt  = (__half*)devPtr(g_hvt);
    __half* hctx = (__half*)devPtr(g_hctx);
    __half* hx2b = (__half*)devPtr(g_hx2b);
    __half* hemid= (__half*)devPtr(g_hemid);
    float* x2b  = (float*)devPtr(g_x2b);
    float* xres = (float*)devPtr(g_xres);
    unsigned* mb = (unsigned*)devPtr(g_mb);
    int* counts = (int*)devPtr(g_counts);
    int* etok   = (int*)devPtr(g_etok);
    float* wslot= (float*)devPtr(g_wslot);

    __half* hq = hqk;
    __half* hk = hqk + (ll)TT * DD;

    auto kDP = tcgd<0,1,0,1>;                 // dual proj (ZSEL, VT for z==2)
    auto kDM = tcgd<1,0,1,0>;                 // dual MoE up (gather, per-z)
    auto kO1 = tcg<128,256,2,8,1,0,0>;        // oproj + residual -> xres & out
    auto kM2 = tcg<128,256,2,8,2,0,1>;        // moe down + fused combine (atomic)

    int smD  = (2 * (64 * 40 + 2 * 32 * 136)) * 2 + 256;
    int smP  = (3 * (128 * 40 + 32 * 264)) * 2 + 256;
    int smFL = (128 * QSH + 4 * 64 * QSH) * 2;
    cudaFuncSetAttribute(kDP, cudaFuncAttributeMaxDynamicSharedMemorySize, smD);
    cudaFuncSetAttribute(kDM, cudaFuncAttributeMaxDynamicSharedMemorySize, smD);
    cudaFuncSetAttribute(kO1, cudaFuncAttributeMaxDynamicSharedMemorySize, smP);
    cudaFuncSetAttribute(kM2, cudaFuncAttributeMaxDynamicSharedMemorySize, smP);
    cudaFuncSetAttribute(flash_k, cudaFuncAttributeMaxDynamicSharedMemorySize, smFL);

    // 0) weight conversion: 2 batched launches
    Ptr7 p7; p7.p[0] = wq1; p7.p[1] = wq2; p7.p[2] = wk1; p7.p[3] = wk2;
    p7.p[4] = wv1; p7.p[5] = wv2; p7.p[6] = wo;
    cvt7_k<<<dim3(WP / 2048, 7), 256>>>(p7, hw);
    Ptr3 p3; p3.p[0] = ew1; p3.p[1] = ew3; p3.p[2] = ew2;
    cvt3_k<<<dim3((int)(NE / 2048), 3), 256>>>(p3, hw + OFF_E1);

    // 1) LN1 (fp16) + mask bitpack
    ln_k<<<TT, 256>>>(x, ln1g, ln1b, hx2a, nullptr);
    packmask_k<<<TT / 8, 256>>>(mask, mb);

    // 2) fused SwiGLU projections; z=2 writes V transposed fp16
    kDP<<<dim3(TT/64, DD/128, 3), 256, smD>>>(hx2a, DD,
        hw + OFF_Q1, hw + OFF_K1, hw + OFF_V1,
        hw + OFF_Q2, hw + OFF_K2, hw + OFF_V2, DD, 0,
        bq1, bk1, bv1, bq2, bk2, bv2, 0,
        hqk, DD, (ll)TT * DD, hvt,
        TT, nullptr, DD, nullptr);

    // 3+4) flash attention (fp16)
    flash_k<<<dim3(SS / 128, BB * HH), 256, smFL>>>(hq, hk, hvt, mb, hctx);

    // 5) out proj + residual -> xres AND out (combine base)
    kO1<<<dim3(TT/128, DD/256, 1), 512, smP>>>(hctx, DD, 0,
        hw + OFF_WO, DD, 0, bo, 0, x, out, nullptr,
        xres, DD, 0,
        TT, nullptr, DD, nullptr);

    // 6) LN2 (fp16 + fp32 for gate)
    ln_k<<<TT, 256>>>(xres, ln2g, ln2b, hx2b, x2b);

    // 7) gate + routing (records per-slot weights)
    zero_counts_k<<<1, 32>>>(counts);
    gate_route_k<<<TT, 256>>>(x2b, gw, gb, counts, etok, wslot);

    // 8) MoE: dual up-proj (fp16) + down-proj with fused weighted-combine into out
    kDM<<<dim3(TT/64, FF/128, EE), 256, smD>>>(hx2b, DD,
        hw + OFF_E1, nullptr, nullptr, hw + OFF_E3, nullptr, nullptr, FF, (ll)DD * FF,
        eb1, nullptr, nullptr, eb3, nullptr, nullptr, FF,
        hemid, FF, (ll)TT * FF, nullptr,
        0, counts, DD, etok);
    kM2<<<dim3(TT/128, DD/256, EE), 512, smP>>>(hemid, FF, (ll)TT * FF,
        hw + OFF_E2, DD, (ll)FF * DD, eb2, DD, nullptr, nullptr, wslot,
        out, DD, 0,
        0, counts, FF, etok);
}

// round 17
// speedup vs baseline: 1.5876x; 1.0522x over previous
#include <cuda_runtime.h>
#include <cuda_fp16.h>
#include <math.h>
#include <stdint.h>

// Problem dims
#define BB 4
#define SS 1024
#define DD 1024
#define FF 2048
#define HH 16
#define EE 8
#define DK 64
#define TT (BB*SS)          // 4096 tokens
typedef long long ll;

// fp16 weight scratch offsets (halves)
#define WP (DD*DD)
#define NE ((ll)EE*DD*FF)
#define OFF_Q1 0
#define OFF_Q2 (1*WP)
#define OFF_K1 (2*WP)
#define OFF_K2 (3*WP)
#define OFF_V1 (4*WP)
#define OFF_V2 (5*WP)
#define OFF_WO (6*WP)
#define OFF_E1 ((ll)7*WP)
#define OFF_E3 (OFF_E1 + NE)
#define OFF_E2 (OFF_E3 + NE)
#define HW_TOTAL (OFF_E2 + (ll)EE*FF*DD)

// ---------------- static device scratch ----------------
__device__ __half g_hw[HW_TOTAL];               // fp16 weights (~115MB)
__device__ __half g_hx2a[TT*DD];
__device__ __half g_hqkv[3*TT*DD];              // q,k,v fp16
__device__ __half g_hctx[TT*DD];
__device__ __half g_hx2b[TT*DD];
__device__ __half g_hemid[(size_t)EE*TT*FF];    // MoE mid fp16
__device__ float g_x2b[TT*DD];                  // fp32 copy for gate
__device__ float g_xres[TT*DD];
__device__ unsigned g_mb[(size_t)TT*32];
__device__ int   g_counts[EE];
__device__ int   g_etok[EE*TT];
__device__ float g_wslot[EE*TT];

// ---------------- helpers ----------------
__device__ __forceinline__ float blockReduceSum(float v, float* sh) {
    int tid = threadIdx.x;
    sh[tid] = v; __syncthreads();
    for (int s = 128; s > 0; s >>= 1) {
        if (tid < s) sh[tid] += sh[tid + s];
        __syncthreads();
    }
    float r = sh[0]; __syncthreads();
    return r;
}
__device__ __forceinline__ void mma16(float4& d, const uint32_t* a, const uint32_t* b) {
    asm volatile(
        "mma.sync.aligned.m16n8k16.row.col.f32.f16.f16.f32 "
        "{%0,%1,%2,%3}, {%4,%5,%6,%7}, {%8,%9}, {%0,%1,%2,%3};"
        : "+f"(d.x), "+f"(d.y), "+f"(d.z), "+f"(d.w)
        : "r"(a[0]), "r"(a[1]), "r"(a[2]), "r"(a[3]), "r"(b[0]), "r"(b[1]));
}
__device__ __forceinline__ void cpa16(void* dst, const void* src, int sz) {
    uint32_t d = (uint32_t)__cvta_generic_to_shared(dst);
    asm volatile("cp.async.cg.shared.global [%0], [%1], 16, %2;\n"
                 :: "r"(d), "l"(src), "r"(sz));
}
__device__ __forceinline__ void ldsm4(uint32_t* d, const __half* p) {
    uint32_t a = (uint32_t)__cvta_generic_to_shared(p);
    asm volatile("ldmatrix.sync.aligned.m8n8.x4.shared.b16 {%0,%1,%2,%3}, [%4];"
                 : "=r"(d[0]), "=r"(d[1]), "=r"(d[2]), "=r"(d[3]) : "r"(a));
}
__device__ __forceinline__ void ldsm4t(uint32_t* d, const __half* p) {
    uint32_t a = (uint32_t)__cvta_generic_to_shared(p);
    asm volatile("ldmatrix.sync.aligned.m8n8.x4.trans.shared.b16 {%0,%1,%2,%3}, [%4];"
                 : "=r"(d[0]), "=r"(d[1]), "=r"(d[2]), "=r"(d[3]) : "r"(a));
}
__device__ __forceinline__ float siluf(float x) {
    return x / (1.f + __expf(-x));
}

// ---------------- batched fp32 -> fp16 convert ----------------
struct Ptr7 { const float* p[7]; };
__global__ void cvt7_k(Ptr7 ps, __half* __restrict__ dst) {
    int z = blockIdx.y;
    ll i = ((ll)blockIdx.x * 256 + threadIdx.x) * 8;
    if (i >= WP) return;
    const float* s = ps.p[z] + i;
    __half2* d = (__half2*)(dst + (ll)z * WP + i);
    float4 v0 = *(const float4*)s;
    float4 v1 = *(const float4*)(s + 4);
    d[0] = __floats2half2_rn(v0.x, v0.y);
    d[1] = __floats2half2_rn(v0.z, v0.w);
    d[2] = __floats2half2_rn(v1.x, v1.y);
    d[3] = __floats2half2_rn(v1.z, v1.w);
}
struct Ptr3 { const float* p[3]; };
__global__ void cvt3_k(Ptr3 ps, __half* __restrict__ dst) {
    int z = blockIdx.y;
    ll i = ((ll)blockIdx.x * 256 + threadIdx.x) * 8;
    if (i >= NE) return;
    const float* s = ps.p[z] + i;
    __half2* d = (__half2*)(dst + (ll)z * NE + i);
    float4 v0 = *(const float4*)s;
    float4 v1 = *(const float4*)(s + 4);
    d[0] = __floats2half2_rn(v0.x, v0.y);
    d[1] = __floats2half2_rn(v0.z, v0.w);
    d[2] = __floats2half2_rn(v1.x, v1.y);
    d[3] = __floats2half2_rn(v1.z, v1.w);
}

// ---------------- LayerNorm (fp16 out, optional fp32 out) ----------------
__global__ void ln_k(const float* __restrict__ x, const float* __restrict__ g,
                     const float* __restrict__ b, __half* __restrict__ out16,
                     float* __restrict__ out32) {
    __shared__ float sh[256];
    int r = blockIdx.x;
    const float* row = x + (size_t)r * DD;
    float s = 0.f;
    for (int i = threadIdx.x; i < DD; i += 256) s += row[i];
    float mean = blockReduceSum(s, sh) * (1.0f / DD);
    float v = 0.f;
    for (int i = threadIdx.x; i < DD; i += 256) {
        float d = row[i] - mean; v += d * d;
    }
    float var = blockReduceSum(v, sh) * (1.0f / DD);
    float inv = rsqrtf(var + 1e-5f);
    for (int i = threadIdx.x; i < DD; i += 256) {
        float val = (row[i] - mean) * inv * g[i] + b[i];
        out16[(size_t)r * DD + i] = __float2half(val);
        if (out32) out32[(size_t)r * DD + i] = val;
    }
}

// ---------------- mask bitpack ----------------
__global__ void packmask_k(const int* __restrict__ mask, unsigned* __restrict__ mb) {
    int wid = threadIdx.x >> 5, lane = threadIdx.x & 31;
    ll row = (ll)blockIdx.x * 8 + wid;
    const int* mrow = mask + row * SS;
#pragma unroll
    for (int w = 0; w < 32; w++) {
        unsigned word = __ballot_sync(0xffffffff, mrow[w * 32 + lane] != 0);
        if (lane == 0) mb[row * 32 + w] = word;
    }
}

// ================= fp16 tensor-core GEMM (single, 3-stage, BK=32) =================
// EPI: 0 = +bias; 1 = +bias + S residual -> C and Caux;
//      2 = atomicAdd(C[tok[r]] , wsl[r]*(acc+bias))  [fused MoE combine]
template<int BM, int BN, int WGM, int WGN, int EPI, int GATHER, int MPZ>
__global__ void __launch_bounds__(WGM*WGN*32)
tcg(const __half* __restrict__ A, int lda, ll sAz,
    const __half* __restrict__ B0, int ldb, ll sBz,
    const float* __restrict__ bias0, ll sBiasZ,
    const float* __restrict__ S, float* __restrict__ Caux,
    const float* __restrict__ wsl0,
    float* __restrict__ C, int ldc, ll sCz,
    int M, const int* __restrict__ Mptr, int Kd,
    const int* __restrict__ tok) {
    constexpr int NTH = WGM * WGN * 32;
    constexpr int BK = 32;
    constexpr int ASTR = BK + 8;
    constexpr int BSTR = BN + 8;
    constexpr int ASZ = BM * ASTR;
    constexpr int BSZ = BK * BSTR;
    constexpr int STG = ASZ + BSZ;
    constexpr int WM = BM / WGM;
    constexpr int WN = BN / WGN;
    constexpr int MT = WM / 16;
    constexpr int NT = WN / 8;

    int zb = blockIdx.z;
    if (MPZ) M = Mptr[zb];
    else if (Mptr) M = *Mptr;
    int bm0 = blockIdx.x * BM;
    if (bm0 >= M) return;
    int bn0 = blockIdx.y * BN;

    const __half* Bm = B0 + (ll)zb * sBz;
    const float* bias = bias0 ? bias0 + (ll)zb * sBiasZ : nullptr;
    A += (ll)zb * sAz;
    C += (ll)zb * sCz;
    const float* wsl = wsl0;
    if (MPZ && tok) tok += (ll)zb * TT;
    if (MPZ && wsl) wsl += (ll)zb * TT;

    extern __shared__ __half smh[];
    int* toks = (int*)(smh + 3 * STG);
    int tid = threadIdx.x;

    if (GATHER) {
        for (int i = tid; i < BM; i += NTH) {
            int gr = bm0 + i;
            toks[i] = (gr < M) ? tok[gr] : -1;
        }
        __syncthreads();
    }

    int wid = tid >> 5, lane = tid & 31;
    int wm = wid / WGN, wn = wid - wm * WGN;
    int lr = lane >> 2, lc = lane & 3;

    int aoffA[MT];
#pragma unroll
    for (int mt = 0; mt < MT; mt++)
        aoffA[mt] = (wm * WM + mt * 16 + (lane & 15)) * ASTR + (lane >> 4) * 8;
    int krow = (lane & 7) + ((lane >> 3) & 1) * 8;
    int ncol = (lane >> 4) * 8;

    auto fill = [&](int st, int k0) {
        __half* As = smh + st * STG;
        __half* Bs = As + ASZ;
#pragma unroll
        for (int it = 0; it < BM * 4 / NTH; it++) {
            int i = it * NTH + tid;
            int row = i >> 2, c8 = i & 3;
            __half* dst = As + row * ASTR + c8 * 8;
            const __half* src;
            int sz = 16;
            if (GATHER) {
                int tk = toks[row];
                src = A + (ll)(tk < 0 ? 0 : tk) * lda + k0 + c8 * 8;
                if (tk < 0) sz = 0;
            } else {
                src = A + (ll)(bm0 + row) * lda + k0 + c8 * 8;
            }
            cpa16(dst, src, sz);
        }
        constexpr int RC = BN / 8;
#pragma unroll
        for (int it = 0; it < BK * RC / NTH; it++) {
            int i = it * NTH + tid;
            int kk = i / RC, c8 = i - kk * RC;
            cpa16(Bs + kk * BSTR + c8 * 8,
                  Bm + (ll)(k0 + kk) * ldb + bn0 + c8 * 8, 16);
        }
    };

    float4 acc[MT][NT];
#pragma unroll
    for (int i = 0; i < MT; i++)
#pragma unroll
        for (int j = 0; j < NT; j++) acc[i][j] = make_float4(0.f, 0.f, 0.f, 0.f);

    int nIt = Kd / BK;
    fill(0, 0);
    asm volatile("cp.async.commit_group;\n");
    if (nIt > 1) {
        fill(1, BK);
        asm volatile("cp.async.commit_group;\n");
    }

    for (int itK = 0; itK < nIt; itK++) {
        if (itK + 1 < nIt) asm volatile("cp.async.wait_group 1;\n");
        else               asm volatile("cp.async.wait_group 0;\n");
        __syncthreads();
        const __half* As = smh + (itK % 3) * STG;
        const __half* Bs = As + ASZ;
#pragma unroll
        for (int ks = 0; ks < 2; ks++) {
            uint32_t af[MT][4];
#pragma unroll
            for (int mt = 0; mt < MT; mt++)
                ldsm4(af[mt], As + aoffA[mt] + ks * 16);
            uint32_t bf[NT][2];
#pragma unroll
            for (int np = 0; np < NT / 2; np++) {
                uint32_t t4[4];
                ldsm4t(t4, Bs + (ks * 16 + krow) * BSTR + wn * WN + np * 16 + ncol);
                bf[2 * np][0] = t4[0]; bf[2 * np][1] = t4[1];
                bf[2 * np + 1][0] = t4[2]; bf[2 * np + 1][1] = t4[3];
            }
#pragma unroll
            for (int mt = 0; mt < MT; mt++)
#pragma unroll
                for (int nt = 0; nt < NT; nt++)
                    mma16(acc[mt][nt], af[mt], bf[nt]);
        }
        if (itK + 2 < nIt) {
            fill((itK + 2) % 3, (itK + 2) * BK);
            asm volatile("cp.async.commit_group;\n");
        }
    }

#pragma unroll
    for (int mt = 0; mt < MT; mt++) {
        int r0 = bm0 + wm * WM + mt * 16 + lr;
        int r1 = r0 + 8;
        int t0 = 0, t1 = 0;
        float ws0 = 0.f, ws1 = 0.f;
        if (EPI == 2) {
            if (r0 < M) { t0 = tok[r0]; ws0 = wsl[r0]; }
            if (r1 < M) { t1 = tok[r1]; ws1 = wsl[r1]; }
        }
#pragma unroll
        for (int nt = 0; nt < NT; nt++) {
            int col = bn0 + wn * WN + nt * 8 + lc * 2;
            float v0 = acc[mt][nt].x, v1 = acc[mt][nt].y;
            float v2 = acc[mt][nt].z, v3 = acc[mt][nt].w;
            if (bias) {
                float b0 = bias[col], b1 = bias[col + 1];
                v0 += b0; v1 += b1; v2 += b0; v3 += b1;
            }
            if (EPI == 2) {
                if (r0 < M) {
                    atomicAdd(&C[(ll)t0 * ldc + col],     ws0 * v0);
                    atomicAdd(&C[(ll)t0 * ldc + col + 1], ws0 * v1);
                }
                if (r1 < M) {
                    atomicAdd(&C[(ll)t1 * ldc + col],     ws1 * v2);
                    atomicAdd(&C[(ll)t1 * ldc + col + 1], ws1 * v3);
                }
            } else {
                if (EPI == 1) {
                    if (r0 < M) {
                        v0 += S[(ll)r0 * ldc + col];
                        v1 += S[(ll)r0 * ldc + col + 1];
                    }
                    if (r1 < M) {
                        v2 += S[(ll)r1 * ldc + col];
                        v3 += S[(ll)r1 * ldc + col + 1];
                    }
                }
                if (r0 < M) {
                    C[(ll)r0 * ldc + col] = v0;
                    C[(ll)r0 * ldc + col + 1] = v1;
                    if (EPI == 1) {
                        Caux[(ll)r0 * ldc + col] = v0;
                        Caux[(ll)r0 * ldc + col + 1] = v1;
                    }
                }
                if (r1 < M) {
                    C[(ll)r1 * ldc + col] = v2;
                    C[(ll)r1 * ldc + col + 1] = v3;
                    if (EPI == 1) {
                        Caux[(ll)r1 * ldc + col] = v2;
                        Caux[(ll)r1 * ldc + col + 1] = v3;
                    }
                }
            }
        }
    }
}

// ================= fp16 dual GEMM (BK=64): out = silu(A@Wa+ba)*(A@Wb+bb), fp16 out =================
// BM=64, BN=128, 8 warps (2x4), 256 thr, 2-stage, 1 barrier/iter, 2 CTAs/SM.
template<int GATHER, int ZSEL, int MPZ>
__global__ void __launch_bounds__(256, 2)
tcgd(const __half* __restrict__ A, int lda,
     const __half* __restrict__ Ba0, const __half* __restrict__ Ba1, const __half* __restrict__ Ba2,
     const __half* __restrict__ Bb0, const __half* __restrict__ Bb1, const __half* __restrict__ Bb2,
     int ldb, ll sBz,
     const float* __restrict__ ba0, const float* __restrict__ ba1, const float* __restrict__ ba2,
     const float* __restrict__ bb0, const float* __restrict__ bb1, const float* __restrict__ bb2,
     ll sBiasZ,
     __half* __restrict__ C, int ldc, ll sCz,
     int M, const int* __restrict__ Mptr, int Kd,
     const int* __restrict__ tok) {
    constexpr int NTH = 256;
    constexpr int BM = 64, BN = 128, BK = 64;
    constexpr int ASTR = BK + 8, BSTR = BN + 8;
    constexpr int ASZ = BM * ASTR, BSZ = BK * BSTR;
    constexpr int STG = ASZ + 2 * BSZ;
    constexpr int MT = 2, NT = 4;

    int zb = blockIdx.z;
    if (MPZ) M = Mptr[zb];
    int bm0 = blockIdx.x * BM;
    if (bm0 >= M) return;
    int bn0 = blockIdx.y * BN;

    const __half* BA = ZSEL ? (zb == 0 ? Ba0 : (zb == 1 ? Ba1 : Ba2)) : Ba0 + (ll)zb * sBz;
    const __half* BBp = ZSEL ? (zb == 0 ? Bb0 : (zb == 1 ? Bb1 : Bb2)) : Bb0 + (ll)zb * sBz;
    const float* biasA = ZSEL ? (zb == 0 ? ba0 : (zb == 1 ? ba1 : ba2)) : ba0 + (ll)zb * sBiasZ;
    const float* biasB = ZSEL ? (zb == 0 ? bb0 : (zb == 1 ? bb1 : bb2)) : bb0 + (ll)zb * sBiasZ;
    C += (ll)zb * sCz;
    if (GATHER && MPZ) tok += (ll)zb * TT;

    extern __shared__ __half smh[];
    int* toks = (int*)(smh + 2 * STG);
    int tid = threadIdx.x;

    if (GATHER) {
        for (int i = tid; i < BM; i += NTH) {
            int gr = bm0 + i;
            toks[i] = (gr < M) ? tok[gr] : -1;
        }
        __syncthreads();
    }

    int wid = tid >> 5, lane = tid & 31;
    int wm = wid >> 2, wn = wid & 3;
    int lr = lane >> 2, lc = lane & 3;

    int aoffA[MT];
#pragma unroll
    for (int mt = 0; mt < MT; mt++)
        aoffA[mt] = (wm * 32 + mt * 16 + (lane & 15)) * ASTR + (lane >> 4) * 8;
    int krow = (lane & 7) + ((lane >> 3) & 1) * 8;
    int ncol = (lane >> 4) * 8;

    auto fill = [&](int st, int k0) {
        __half* As = smh + st * STG;
        __half* Bsa = As + ASZ;
        __half* Bsb = Bsa + BSZ;
        // A: 64 rows x 8 chunks
#pragma unroll
        for (int it = 0; it < 2; it++) {
            int i = it * NTH + tid;
            int row = i >> 3, c8 = i & 7;
            __half* dst = As + row * ASTR + c8 * 8;
            const __half* src;
            int sz = 16;
            if (GATHER) {
                int tk = toks[row];
                src = A + (ll)(tk < 0 ? 0 : tk) * lda + k0 + c8 * 8;
                if (tk < 0) sz = 0;
            } else {
                src = A + (ll)(bm0 + row) * lda + k0 + c8 * 8;
            }
            cpa16(dst, src, sz);
        }
        // B: 64 k-rows x 16 chunks, two tensors
#pragma unroll
        for (int it = 0; it < 4; it++) {
            int i = it * NTH + tid;
            int kk = i >> 4, c8 = i & 15;
            cpa16(Bsa + kk * BSTR + c8 * 8, BA  + (ll)(k0 + kk) * ldb + bn0 + c8 * 8, 16);
            cpa16(Bsb + kk * BSTR + c8 * 8, BBp + (ll)(k0 + kk) * ldb + bn0 + c8 * 8, 16);
        }
    };

    float4 accA[MT][NT], accB[MT][NT];
#pragma unroll
    for (int i = 0; i < MT; i++)
#pragma unroll
        for (int j = 0; j < NT; j++) {
            accA[i][j] = make_float4(0.f, 0.f, 0.f, 0.f);
            accB[i][j] = make_float4(0.f, 0.f, 0.f, 0.f);
        }

    int nIt = Kd / BK;
    fill(0, 0);
    asm volatile("cp.async.commit_group;\n");

    for (int itK = 0; itK < nIt; itK++) {
        asm volatile("cp.async.wait_group 0;\n");
        __syncthreads();
        if (itK + 1 < nIt) {
            fill((itK + 1) & 1, (itK + 1) * BK);
            asm volatile("cp.async.commit_group;\n");
        }
        const __half* As = smh + (itK & 1) * STG;
        const __half* Bsa = As + ASZ;
        const __half* Bsb = Bsa + BSZ;
#pragma unroll
        for (int ks = 0; ks < 4; ks++) {
            uint32_t af[MT][4];
#pragma unroll
            for (int mt = 0; mt < MT; mt++)
                ldsm4(af[mt], As + aoffA[mt] + ks * 16);
            uint32_t bfa[NT][2], bfb[NT][2];
#pragma unroll
            for (int np = 0; np < 2; np++) {
                uint32_t t4[4];
                ldsm4t(t4, Bsa + (ks * 16 + krow) * BSTR + wn * 32 + np * 16 + ncol);
                bfa[2 * np][0] = t4[0]; bfa[2 * np][1] = t4[1];
                bfa[2 * np + 1][0] = t4[2]; bfa[2 * np + 1][1] = t4[3];
                ldsm4t(t4, Bsb + (ks * 16 + krow) * BSTR + wn * 32 + np * 16 + ncol);
                bfb[2 * np][0] = t4[0]; bfb[2 * np][1] = t4[1];
                bfb[2 * np + 1][0] = t4[2]; bfb[2 * np + 1][1] = t4[3];
            }
#pragma unroll
            for (int mt = 0; mt < MT; mt++)
#pragma unroll
                for (int nt = 0; nt < NT; nt++) {
                    mma16(accA[mt][nt], af[mt], bfa[nt]);
                    mma16(accB[mt][nt], af[mt], bfb[nt]);
                }
        }
    }

#pragma unroll
    for (int mt = 0; mt < MT; mt++) {
        int r0 = bm0 + wm * 32 + mt * 16 + lr;
        int r1 = r0 + 8;
#pragma unroll
        for (int nt = 0; nt < NT; nt++) {
            int col = bn0 + wn * 32 + nt * 8 + lc * 2;
            float ba_ = biasA[col], ba1_ = biasA[col + 1];
            float bb_ = biasB[col], bb1_ = biasB[col + 1];
            float o0 = siluf(accA[mt][nt].x + ba_)  * (accB[mt][nt].x + bb_);
            float o1 = siluf(accA[mt][nt].y + ba1_) * (accB[mt][nt].y + bb1_);
            float o2 = siluf(accA[mt][nt].z + ba_)  * (accB[mt][nt].z + bb_);
            float o3 = siluf(accA[mt][nt].w + ba1_) * (accB[mt][nt].w + bb1_);
            if (r0 < M)
                *(__half2*)(C + (ll)r0 * ldc + col) = __floats2half2_rn(o0, o1);
            if (r1 < M)
                *(__half2*)(C + (ll)r1 * ldc + col) = __floats2half2_rn(o2, o3);
        }
    }
}

// ================= flash attention (fp16, warp-local softmax, natural V) =================
#define QSH 72
__global__ void __launch_bounds__(256, 2)
flash_k(const __half* __restrict__ qg, const __half* __restrict__ kg,
        const __half* __restrict__ vg, const unsigned* __restrict__ mb,
        __half* __restrict__ ctx) {
    extern __shared__ __half smh[];
    __half* Qs = smh;
    __half* Ks = smh + 128 * QSH;
    __half* Vs = Ks + 2 * 64 * QSH;        // [key][dk] natural layout
    __half* Ps = Qs;

    int tid = threadIdx.x;
    int z = blockIdx.y;
    int b = z / HH, h = z % HH;
    int q0 = blockIdx.x * 128;
    int lane = tid & 31, wid = tid >> 5;
    int lr = lane >> 2, lc = lane & 3;

    const __half* Qg = qg + ((ll)(b * SS + q0)) * DD + h * DK;
#pragma unroll
    for (int it = 0; it < 4; it++) {
        int i = it * 256 + tid;
        int row = i >> 3, c8 = i & 7;
        cpa16(Qs + row * QSH + c8 * 8, Qg + (ll)row * DD + c8 * 8, 16);
    }
    asm volatile("cp.async.commit_group;\n");

    auto pf = [&](int i) {
        int st = i & 1;
        const __half* Kg = kg + ((ll)(b * SS + i * 64)) * DD + h * DK;
        const __half* Vg = vg + ((ll)(b * SS + i * 64)) * DD + h * DK;
#pragma unroll
        for (int it = 0; it < 2; it++) {
            int j = it * 256 + tid;
            int row = j >> 3, c8 = j & 7;
            cpa16(Ks + st * 64 * QSH + row * QSH + c8 * 8, Kg + (ll)row * DD + c8 * 8, 16);
        }
#pragma unroll
        for (int it = 0; it < 2; it++) {
            int j = it * 256 + tid;
            int row = j >> 3, c8 = j & 7;   // row = key
            cpa16(Vs + st * 64 * QSH + row * QSH + c8 * 8, Vg + (ll)row * DD + c8 * 8, 16);
        }
    };
    pf(0);
    asm volatile("cp.async.commit_group;\n");

    asm volatile("cp.async.wait_group 1;\n");
    __syncthreads();
    uint32_t qf[4][4];
    int aoffQ = (wid * 16 + (lane & 15)) * QSH + (lane >> 4) * 8;
#pragma unroll
    for (int ks = 0; ks < 4; ks++) ldsm4(qf[ks], Qs + aoffQ + ks * 16);

    // no-trans B offsets (K path): brow over n(keys), bkof over k(dk)
    int brow = (lane & 7) + (lane >> 4) * 8;
    int bkof = ((lane >> 3) & 1) * 8;
    // trans B offsets (V path): krow over k(keys), ncol over n(dk)
    int krow = (lane & 7) + ((lane >> 3) & 1) * 8;
    int ncol = (lane >> 4) * 8;

    float4 oacc[8];
#pragma unroll
    for (int nt = 0; nt < 8; nt++) oacc[nt] = make_float4(0.f, 0.f, 0.f, 0.f);
    float m0 = -1e30f, m1 = -1e30f, l0 = 0.f, l1 = 0.f;
    int r0 = wid * 16 + lr, r1 = r0 + 8;
    const uint2* mp0 = (const uint2*)(mb + ((ll)(b * SS + q0 + r0)) * 32);
    const uint2* mp1 = (const uint2*)(mb + ((ll)(b * SS + q0 + r1)) * 32);

    constexpr int NIT = SS / 64;
    for (int i = 0; i < NIT; i++) {
        asm volatile("cp.async.wait_group 0;\n");
        __syncthreads();
        if (i + 1 < NIT) {
            pf(i + 1);
            asm volatile("cp.async.commit_group;\n");
        }
        const __half* Kst = Ks + (i & 1) * 64 * QSH;
        const __half* Vst = Vs + (i & 1) * 64 * QSH;

        float4 s[8];
#pragma unroll
        for (int nt = 0; nt < 8; nt++) s[nt] = make_float4(0.f, 0.f, 0.f, 0.f);
#pragma unroll
        for (int ks = 0; ks < 4; ks++) {
            uint32_t bf[8][2];
#pragma unroll
            for (int p = 0; p < 4; p++) {
                uint32_t t4[4];
                ldsm4(t4, Kst + (p * 16 + brow) * QSH + ks * 16 + bkof);
                bf[2 * p][0] = t4[0]; bf[2 * p][1] = t4[1];
                bf[2 * p + 1][0] = t4[2]; bf[2 * p + 1][1] = t4[3];
            }
#pragma unroll
            for (int nt = 0; nt < 8; nt++) mma16(s[nt], qf[ks], bf[nt]);
        }
        uint2 w0 = mp0[i];
        uint2 w1 = mp1[i];
#pragma unroll
        for (int nt = 0; nt < 8; nt++) {
            int bit = (nt & 3) * 8 + lc * 2;
            unsigned u0 = (nt < 4) ? w0.x : w0.y;
            unsigned u1 = (nt < 4) ? w1.x : w1.y;
            s[nt].x = ((u0 >> bit) & 1u)       ? s[nt].x * 0.125f : -1e9f;
            s[nt].y = ((u0 >> (bit + 1)) & 1u) ? s[nt].y * 0.125f : -1e9f;
            s[nt].z = ((u1 >> bit) & 1u)       ? s[nt].z * 0.125f : -1e9f;
            s[nt].w = ((u1 >> (bit + 1)) & 1u) ? s[nt].w * 0.125f : -1e9f;
        }
        float mx0 = -1e30f, mx1 = -1e30f;
#pragma unroll
        for (int nt = 0; nt < 8; nt++) {
            mx0 = fmaxf(mx0, fmaxf(s[nt].x, s[nt].y));
            mx1 = fmaxf(mx1, fmaxf(s[nt].z, s[nt].w));
        }
#pragma unroll
        for (int o = 1; o <= 2; o <<= 1) {
            mx0 = fmaxf(mx0, __shfl_xor_sync(0xffffffff, mx0, o));
            mx1 = fmaxf(mx1, __shfl_xor_sync(0xffffffff, mx1, o));
        }
        float nm0 = fmaxf(m0, mx0), nm1 = fmaxf(m1, mx1);
        float sc0 = __expf(m0 - nm0), sc1 = __expf(m1 - nm1);
        m0 = nm0; m1 = nm1;
        float su0 = 0.f, su1 = 0.f;
#pragma unroll
        for (int nt = 0; nt < 8; nt++) {
            int col = nt * 8 + lc * 2;
            float e0 = __expf(s[nt].x - m0), e1 = __expf(s[nt].y - m0);
            float e2 = __expf(s[nt].z - m1), e3 = __expf(s[nt].w - m1);
            su0 += e0 + e1; su1 += e2 + e3;
            *(__half2*)(Ps + r0 * QSH + col) = __floats2half2_rn(e0, e1);
            *(__half2*)(Ps + r1 * QSH + col) = __floats2half2_rn(e2, e3);
        }
#pragma unroll
        for (int o = 1; o <= 2; o <<= 1) {
            su0 += __shfl_xor_sync(0xffffffff, su0, o);
            su1 += __shfl_xor_sync(0xffffffff, su1, o);
        }
        l0 = l0 * sc0 + su0;
        l1 = l1 * sc1 + su1;
#pragma unroll
        for (int nt = 0; nt < 8; nt++) {
            oacc[nt].x *= sc0; oacc[nt].y *= sc0;
            oacc[nt].z *= sc1; oacc[nt].w *= sc1;
        }
        __syncwarp();
        // O += P @ V   (V [key][dk], trans ldsm -> B fragments)
#pragma unroll
        for (int ks = 0; ks < 4; ks++) {
            uint32_t af[4];
            ldsm4(af, Ps + aoffQ + ks * 16);
            uint32_t bf[8][2];
#pragma unroll
            for (int p = 0; p < 4; p++) {
                uint32_t t4[4];
                ldsm4t(t4, Vst + (ks * 16 + krow) * QSH + p * 16 + ncol);
                bf[2 * p][0] = t4[0]; bf[2 * p][1] = t4[1];
                bf[2 * p + 1][0] = t4[2]; bf[2 * p + 1][1] = t4[3];
            }
#pragma unroll
            for (int nt = 0; nt < 8; nt++) mma16(oacc[nt], af, bf[nt]);
        }
    }

    float inv0 = 1.f / l0, inv1 = 1.f / l1;
    __half* cg = ctx + ((ll)(b * SS + q0)) * DD + h * DK;
#pragma unroll
    for (int nt = 0; nt < 8; nt++) {
        int col = nt * 8 + lc * 2;
        *(__half2*)(cg + (ll)r0 * DD + col) = __floats2half2_rn(oacc[nt].x * inv0, oacc[nt].y * inv0);
        *(__half2*)(cg + (ll)r1 * DD + col) = __floats2half2_rn(oacc[nt].z * inv1, oacc[nt].w * inv1);
    }
}

// ---------------- gate + routing ----------------
__global__ void zero_counts_k(int* counts) {
    if (threadIdx.x < EE) counts[threadIdx.x] = 0;
}
__global__ void gate_route_k(const float* __restrict__ x2, const float* __restrict__ gw,
                             const float* __restrict__ gb, int* counts, int* etok,
                             float* wslot) {
    int t = blockIdx.x;
    __shared__ float xs[DD];
    __shared__ float logits[EE];
    const float* row = x2 + (ll)t * DD;
    for (int i = threadIdx.x; i < DD; i += 256) xs[i] = row[i];
    __syncthreads();
    int w = threadIdx.x / 32, lane = threadIdx.x % 32;
    float s = 0.f;
    for (int d = lane; d < DD; d += 32) s += xs[d] * gw[d * EE + w];
    for (int o = 16; o; o >>= 1) s += __shfl_xor_sync(0xffffffff, s, o);
    if (lane == 0) logits[w] = s + gb[w];
    __syncthreads();
    if (threadIdx.x == 0) {
        float p[EE];
        float m = -1e30f;
        for (int e = 0; e < EE; e++) m = fmaxf(m, logits[e]);
        float sum = 0.f;
        for (int e = 0; e < EE; e++) { p[e] = __expf(logits[e] - m); sum += p[e]; }
        for (int e = 0; e < EE; e++) p[e] /= sum;
        int i0 = 0;
        for (int e = 1; e < EE; e++) if (p[e] > p[i0]) i0 = e;
        int i1 = -1;
        for (int e = 0; e < EE; e++) {
            if (e == i0) continue;
            if (i1 < 0 || p[e] > p[i1]) i1 = e;
        }
        float denom = p[i0] + p[i1] + 1e-6f;
        int s0 = atomicAdd(&counts[i0], 1);
        int s1 = atomicAdd(&counts[i1], 1);
        etok[i0 * TT + s0] = t;
        etok[i1 * TT + s1] = t;
        wslot[i0 * TT + s0] = p[i0] / denom;
        wslot[i1 * TT + s1] = p[i1] / denom;
    }
}

// ---------------- host side ----------------
static void* devPtr(const void* sym) {
    void* p = nullptr;
    cudaGetSymbolAddress(&p, sym);
    return p;
}

extern "C" void kernel_launch(void* const* d_in, const int* in_sizes, int n_in,
                              void* d_out, int out_size) {
    const float* x    = (const float*)d_in[0];
    const int*   mask = (const int*)  d_in[1];
    const float* wq1 = (const float*)d_in[2];  const float* bq1 = (const float*)d_in[3];
    const float* wq2 = (const float*)d_in[4];  const float* bq2 = (const float*)d_in[5];
    const float* wk1 = (const float*)d_in[6];  const float* bk1 = (const float*)d_in[7];
    const float* wk2 = (const float*)d_in[8];  const float* bk2 = (const float*)d_in[9];
    const float* wv1 = (const float*)d_in[10]; const float* bv1 = (const float*)d_in[11];
    const float* wv2 = (const float*)d_in[12]; const float* bv2 = (const float*)d_in[13];
    const float* wo  = (const float*)d_in[14]; const float* bo  = (const float*)d_in[15];
    const float* ln1g = (const float*)d_in[16]; const float* ln1b = (const float*)d_in[17];
    const float* ln2g = (const float*)d_in[18]; const float* ln2b = (const float*)d_in[19];
    const float* gw  = (const float*)d_in[20]; const float* gb  = (const float*)d_in[21];
    const float* ew1 = (const float*)d_in[22]; const float* eb1 = (const float*)d_in[23];
    const float* ew2 = (const float*)d_in[24]; const float* eb2 = (const float*)d_in[25];
    const float* ew3 = (const float*)d_in[26]; const float* eb3 = (const float*)d_in[27];
    float* out = (float*)d_out;

    __half* hw   = (__half*)devPtr(g_hw);
    __half* hx2a = (__half*)devPtr(g_hx2a);
    __half* hqkv = (__half*)devPtr(g_hqkv);
    __half* hctx = (__half*)devPtr(g_hctx);
    __half* hx2b = (__half*)devPtr(g_hx2b);
    __half* hemid= (__half*)devPtr(g_hemid);
    float* x2b  = (float*)devPtr(g_x2b);
    float* xres = (float*)devPtr(g_xres);
    unsigned* mb = (unsigned*)devPtr(g_mb);
    int* counts = (int*)devPtr(g_counts);
    int* etok   = (int*)devPtr(g_etok);
    float* wslot= (float*)devPtr(g_wslot);

    __half* hq = hqkv;
    __half* hk = hqkv + (ll)TT * DD;
    __half* hv = hqkv + 2ll * TT * DD;

    auto kDP = tcgd<0,1,0>;                   // dual proj (ZSEL)
    auto kDM = tcgd<1,0,1>;                   // dual MoE up (gather, per-z)
    auto kO1 = tcg<128,256,2,8,1,0,0>;        // oproj + residual -> xres & out
    auto kM2 = tcg<128,256,2,8,2,0,1>;        // moe down + fused combine (atomic)

    int smD  = (2 * (64 * 72 + 2 * 64 * 136)) * 2 + 256;    // dual gemm BK=64
    int smP  = (3 * (128 * 40 + 32 * 264)) * 2 + 256;
    int smFL = (128 * QSH + 4 * 64 * QSH) * 2;
    cudaFuncSetAttribute(kDP, cudaFuncAttributeMaxDynamicSharedMemorySize, smD);
    cudaFuncSetAttribute(kDM, cudaFuncAttributeMaxDynamicSharedMemorySize, smD);
    cudaFuncSetAttribute(kO1, cudaFuncAttributeMaxDynamicSharedMemorySize, smP);
    cudaFuncSetAttribute(kM2, cudaFuncAttributeMaxDynamicSharedMemorySize, smP);
    cudaFuncSetAttribute(flash_k, cudaFuncAttributeMaxDynamicSharedMemorySize, smFL);

    // 0) weight conversion: 2 batched launches
    Ptr7 p7; p7.p[0] = wq1; p7.p[1] = wq2; p7.p[2] = wk1; p7.p[3] = wk2;
    p7.p[4] = wv1; p7.p[5] = wv2; p7.p[6] = wo;
    cvt7_k<<<dim3(WP / 2048, 7), 256>>>(p7, hw);
    Ptr3 p3; p3.p[0] = ew1; p3.p[1] = ew3; p3.p[2] = ew2;
    cvt3_k<<<dim3((int)(NE / 2048), 3), 256>>>(p3, hw + OFF_E1);

    // 1) LN1 (fp16) + mask bitpack
    ln_k<<<TT, 256>>>(x, ln1g, ln1b, hx2a, nullptr);
    packmask_k<<<TT / 8, 256>>>(mask, mb);

    // 2) fused SwiGLU projections (q,k,v uniform, coalesced)
    kDP<<<dim3(TT/64, DD/128, 3), 256, smD>>>(hx2a, DD,
        hw + OFF_Q1, hw + OFF_K1, hw + OFF_V1,
        hw + OFF_Q2, hw + OFF_K2, hw + OFF_V2, DD, 0,
        bq1, bk1, bv1, bq2, bk2, bv2, 0,
        hqkv, DD, (ll)TT * DD,
        TT, nullptr, DD, nullptr);

    // 3+4) flash attention (fp16, natural-layout V)
    flash_k<<<dim3(SS / 128, BB * HH), 256, smFL>>>(hq, hk, hv, mb, hctx);

    // 5) out proj + residual -> xres AND out (combine base)
    kO1<<<dim3(TT/128, DD/256, 1), 512, smP>>>(hctx, DD, 0,
        hw + OFF_WO, DD, 0, bo, 0, x, out, nullptr,
        xres, DD, 0,
        TT, nullptr, DD, nullptr);

    // 6) LN2 (fp16 + fp32 for gate)
    ln_k<<<TT, 256>>>(xres, ln2g, ln2b, hx2b, x2b);

    // 7) gate + routing (records per-slot weights)
    zero_counts_k<<<1, 32>>>(counts);
    gate_route_k<<<TT, 256>>>(x2b, gw, gb, counts, etok, wslot);

    // 8) MoE: dual up-proj (fp16) + down-proj with fused weighted-combine into out
    kDM<<<dim3(TT/64, FF/128, EE), 256, smD>>>(hx2b, DD,
        hw + OFF_E1, nullptr, nullptr, hw + OFF_E3, nullptr, nullptr, FF, (ll)DD * FF,
        eb1, nullptr, nullptr, eb3, nullptr, nullptr, FF,
        hemid, FF, (ll)TT * FF,
        0, counts, DD, etok);
    kM2<<<dim3(TT/128, DD/256, EE), 512, smP>>>(hemid, FF, (ll)TT * FF,
        hw + OFF_E2, DD, (ll)FF * DD, eb2, DD, nullptr, nullptr, wslot,
        out, DD, 0,
        0, counts, FF, etok);
}